// round 1
// baseline (speedup 1.0000x reference)
#include <cuda_runtime.h>
#include <cuda_bf16.h>
#include <math.h>

// ---------------------------------------------------------------------------
// CapsNet forward. B=512.
// Pipeline:
//   conv1:  [512,1,28,28] -> relu -> [512,256,20,20]
//   pcconv: stride2 9x9  -> [512,256,6,6] (+bias)
//   squash over 1152 (per (b, group of 32 channels)) -> hT [512,1152,8]
//   u_hat[b,i,k,d] = sum_e W[i,k,d,e]*hT[b,i,e]  -> [512,1152,160]
//   routing x3 -> v [512,10,16]
//   decoder: mask -> fc1 relu -> fc2 relu -> fc3 sigmoid -> dec [512,784]
//   probs = softmax(||v||) [512,10]
// Output layout: [probs (512*10)] then [dec (512*784)]
// ---------------------------------------------------------------------------

#define BATCH 512

// Scratch (device globals; no allocations allowed)
__device__ float g_conv1[BATCH * 256 * 20 * 20];     // 209.7 MB
__device__ float g_pc[BATCH * 256 * 36];             // 18.9 MB
__device__ float g_hT[BATCH * 1152 * 8];             // 18.9 MB
__device__ float g_uhat[BATCH * 1152 * 160];         // 377.5 MB
__device__ float g_blog[BATCH * 1152 * 10];          // 23.6 MB
__device__ float g_v[BATCH * 160];
__device__ float g_m[BATCH * 160];
__device__ float g_fc1[BATCH * 512];
__device__ float g_fc2[BATCH * 1024];

// ---------------------------------------------------------------------------
// conv1: 1->256, 9x9, valid, relu.  grid (512, 4), block 256
// thread = (oc_l in [0,64), yg in [0,4)); each thread does 5 output rows.
// ---------------------------------------------------------------------------
__global__ __launch_bounds__(256) void conv1_kernel(
    const float* __restrict__ x, const float* __restrict__ w,
    const float* __restrict__ bias)
{
    int b = blockIdx.x;
    int ocg = blockIdx.y;
    __shared__ float s_img[784];
    __shared__ float s_w[64 * 81];
    int tid = threadIdx.x;
    for (int i = tid; i < 784; i += 256) s_img[i] = x[b * 784 + i];
    for (int i = tid; i < 64 * 81; i += 256) s_w[i] = w[ocg * 64 * 81 + i];
    __syncthreads();

    int oc_l = tid & 63;
    int yg = tid >> 6;
    int oc = ocg * 64 + oc_l;
    float bv = bias[oc];

    for (int yi = 0; yi < 5; yi++) {
        int y = yg * 5 + yi;
        float acc[20];
        #pragma unroll
        for (int xx = 0; xx < 20; xx++) acc[xx] = 0.f;
        for (int ky = 0; ky < 9; ky++) {
            float rin[28];
            #pragma unroll
            for (int c = 0; c < 28; c++) rin[c] = s_img[(y + ky) * 28 + c];
            #pragma unroll
            for (int kx = 0; kx < 9; kx++) {
                float wv = s_w[oc_l * 81 + ky * 9 + kx];
                #pragma unroll
                for (int xx = 0; xx < 20; xx++) acc[xx] += wv * rin[xx + kx];
            }
        }
        float* out = g_conv1 + ((b * 256 + oc) * 20 + y) * 20;
        #pragma unroll
        for (int xx = 0; xx < 20; xx++) out[xx] = fmaxf(acc[xx] + bv, 0.f);
    }
}

// ---------------------------------------------------------------------------
// pcconv: 256->256, 9x9, stride 2.  grid (512, 4), block 384.
// thread = (oc_l in [0,64), y in [0,6)); 6 output cols per thread.
// Weights staged in smem in 2-ic chunks with padded stride (conflict free).
// ---------------------------------------------------------------------------
#define PC_PW 163  // padded row stride for 162 floats (2 ic * 81)

__global__ __launch_bounds__(384) void pcconv_kernel(
    const float* __restrict__ w, const float* __restrict__ bias)
{
    int b = blockIdx.x;
    int ocg = blockIdx.y;
    __shared__ float s_in[2 * 400];
    __shared__ float s_w[64 * PC_PW];
    int tid = threadIdx.x;
    int oc_l = tid & 63;
    int y = tid >> 6;  // 0..5
    int oc = ocg * 64 + oc_l;

    float acc[6];
    #pragma unroll
    for (int xx = 0; xx < 6; xx++) acc[xx] = 0.f;

    const float* inb = g_conv1 + b * 256 * 400;

    for (int ic0 = 0; ic0 < 256; ic0 += 2) {
        __syncthreads();
        for (int i = tid; i < 800; i += 384) s_in[i] = inb[ic0 * 400 + i];
        for (int i = tid; i < 64 * 162; i += 384) {
            int r = i / 162;
            int e = i - r * 162;
            s_w[r * PC_PW + e] = w[(ocg * 64 + r) * 20736 + ic0 * 81 + e];
        }
        __syncthreads();

        #pragma unroll
        for (int icl = 0; icl < 2; icl++) {
            for (int ky = 0; ky < 9; ky++) {
                int ir = 2 * y + ky;
                float rin[19];
                #pragma unroll
                for (int c = 0; c < 19; c++) rin[c] = s_in[icl * 400 + ir * 20 + c];
                #pragma unroll
                for (int kx = 0; kx < 9; kx++) {
                    float wv = s_w[oc_l * PC_PW + icl * 81 + ky * 9 + kx];
                    #pragma unroll
                    for (int xx = 0; xx < 6; xx++) acc[xx] += wv * rin[2 * xx + kx];
                }
            }
        }
    }

    float bv = bias[oc];
    float* out = g_pc + ((b * 256 + oc) * 6 + y) * 6;
    #pragma unroll
    for (int xx = 0; xx < 6; xx++) out[xx] = acc[xx] + bv;
}

// ---------------------------------------------------------------------------
// squash over 1152 (faithful to source) + transpose to hT[b,1152,8]
// grid 512, block 256 (warp g handles group g)
// ---------------------------------------------------------------------------
__global__ __launch_bounds__(256) void squash_h_kernel()
{
    int b = blockIdx.x;
    int tid = threadIdx.x;
    __shared__ float s_scale[8];
    int g = tid >> 5;
    int lane = tid & 31;
    const float* pb = g_pc + b * 9216;

    float ss = 0.f;
    for (int j = lane; j < 1152; j += 32) {
        float v = pb[g * 1152 + j];
        ss += v * v;
    }
    #pragma unroll
    for (int o = 16; o; o >>= 1) ss += __shfl_xor_sync(0xffffffffu, ss, o);
    if (lane == 0) s_scale[g] = sqrtf(ss) / (1.f + ss);
    __syncthreads();

    for (int idx = tid; idx < 9216; idx += 256) {
        int c = idx / 36;
        int s = idx - c * 36;
        int g2 = c >> 5;
        int pos = ((c & 31) * 36) + s;
        g_hT[(b * 1152 + pos) * 8 + g2] = pb[idx] * s_scale[g2];
    }
}

// ---------------------------------------------------------------------------
// u_hat[b,i,kd] = sum_e W[i,kd,e]*hT[b,i,e].  grid 1152 (i), block 256.
// W staged transposed in smem: sW[e*160 + kd].
// ---------------------------------------------------------------------------
__global__ __launch_bounds__(256) void uhat_kernel(const float* __restrict__ W)
{
    int i = blockIdx.x;
    __shared__ float sW[1280];   // [e][kd]
    __shared__ float sh[32 * 8]; // 32 images x 8 features
    int tid = threadIdx.x;
    for (int j = tid; j < 1280; j += 256) {
        // W flat index j = kd*8 + e  ->  store at e*160 + kd
        sW[(j & 7) * 160 + (j >> 3)] = W[i * 1280 + j];
    }

    for (int b0 = 0; b0 < BATCH; b0 += 32) {
        __syncthreads();
        sh[tid] = g_hT[((b0 + (tid >> 3)) * 1152 + i) * 8 + (tid & 7)];
        __syncthreads();
        if (tid < 160) {
            #pragma unroll 4
            for (int bb = 0; bb < 32; bb++) {
                float u = 0.f;
                #pragma unroll
                for (int e = 0; e < 8; e++) u += sW[e * 160 + tid] * sh[bb * 8 + e];
                g_uhat[((b0 + bb) * 1152 + i) * 160 + tid] = u;
            }
        }
    }
}

// ---------------------------------------------------------------------------
// routing iter 0: c = 1/10 uniformly -> s = 0.1*sum_i u_hat; v = squash_d(s)
// also zeroes the b-logits. grid 512, block 160.
// ---------------------------------------------------------------------------
__global__ __launch_bounds__(160) void routing0_kernel()
{
    int b = blockIdx.x;
    int t = threadIdx.x;  // kd
    for (int j = t; j < 11520; j += 160) g_blog[b * 11520 + j] = 0.f;

    const float* ub = g_uhat + b * 184320;
    float s0 = 0.f, s1 = 0.f, s2 = 0.f, s3 = 0.f;
    for (int i = 0; i < 1152; i += 4) {
        s0 += ub[(i + 0) * 160 + t];
        s1 += ub[(i + 1) * 160 + t];
        s2 += ub[(i + 2) * 160 + t];
        s3 += ub[(i + 3) * 160 + t];
    }
    float s = 0.1f * (s0 + s1 + s2 + s3);

    __shared__ float s_s[160];
    s_s[t] = s;
    __syncthreads();
    int k = t >> 4;
    float n2 = 0.f;
    #pragma unroll
    for (int d = 0; d < 16; d++) {
        float v = s_s[k * 16 + d];
        n2 += v * v;
    }
    g_v[b * 160 + t] = s * (sqrtf(n2) / (1.f + n2));
}

// ---------------------------------------------------------------------------
// routing iter (r=1,2): b += u.v_prev; c = softmax_k(b); s = sum_i c*u;
// v = squash_d(s).  grid 512, block 256.
// ---------------------------------------------------------------------------
__global__ __launch_bounds__(256) void routing_iter_kernel()
{
    int b = blockIdx.x;
    int t = threadIdx.x;
    __shared__ float v_s[160];
    __shared__ float c_s[1152 * 10];
    __shared__ float s_s[160];

    if (t < 160) v_s[t] = g_v[b * 160 + t];
    __syncthreads();

    const float* ub = g_uhat + b * 184320;
    float* blb = g_blog + b * 11520;

    // Phase A: per-i logits update + softmax
    for (int i = t; i < 1152; i += 256) {
        const float4* u4 = (const float4*)(ub + i * 160);
        float bl[10];
        float mx = -1e30f;
        #pragma unroll
        for (int k = 0; k < 10; k++) {
            float dk = 0.f;
            #pragma unroll
            for (int j = 0; j < 4; j++) {
                float4 u = u4[k * 4 + j];
                dk += u.x * v_s[k * 16 + 4 * j + 0];
                dk += u.y * v_s[k * 16 + 4 * j + 1];
                dk += u.z * v_s[k * 16 + 4 * j + 2];
                dk += u.w * v_s[k * 16 + 4 * j + 3];
            }
            float nb = blb[i * 10 + k] + dk;
            blb[i * 10 + k] = nb;
            bl[k] = nb;
            mx = fmaxf(mx, nb);
        }
        float sum = 0.f;
        #pragma unroll
        for (int k = 0; k < 10; k++) {
            float e = __expf(bl[k] - mx);
            bl[k] = e;
            sum += e;
        }
        float inv = 1.f / sum;
        #pragma unroll
        for (int k = 0; k < 10; k++) c_s[i * 10 + k] = bl[k] * inv;
    }
    __syncthreads();

    // Phase B: s accumulation + squash
    float s = 0.f;
    if (t < 160) {
        int k = t >> 4;
        float p0 = 0.f, p1 = 0.f;
        for (int i = 0; i < 1152; i += 2) {
            p0 += c_s[(i + 0) * 10 + k] * __ldg(ub + (i + 0) * 160 + t);
            p1 += c_s[(i + 1) * 10 + k] * __ldg(ub + (i + 1) * 160 + t);
        }
        s = p0 + p1;
    }
    __syncthreads();
    if (t < 160) s_s[t] = s;
    __syncthreads();
    if (t < 160) {
        int k = t >> 4;
        float n2 = 0.f;
        #pragma unroll
        for (int d = 0; d < 16; d++) {
            float v = s_s[k * 16 + d];
            n2 += v * v;
        }
        g_v[b * 160 + t] = s * (sqrtf(n2) / (1.f + n2));
    }
}

// ---------------------------------------------------------------------------
// mask: m[b,kd] = v[b,kd] * labels[b,k]
// ---------------------------------------------------------------------------
__global__ void mask_kernel(const float* __restrict__ labels)
{
    int idx = blockIdx.x * 256 + threadIdx.x;
    if (idx < BATCH * 160) {
        int b = idx / 160;
        int k = (idx - b * 160) >> 4;
        g_m[idx] = g_v[idx] * labels[b * 10 + k];
    }
}

// ---------------------------------------------------------------------------
// GEMM: C[M,N] = act(A[M,K] @ Wt[N,K]^T + bias).  64x64 tile, BK=8,
// 256 threads, 4x4 per thread. SEL picks A/C buffers (device globals).
// ACT: 0 = relu, 1 = sigmoid.
// ---------------------------------------------------------------------------
template <int ACT, int SEL>
__global__ __launch_bounds__(256) void gemm_kernel(
    const float* __restrict__ Wt, const float* __restrict__ bias,
    float* __restrict__ outp, int M, int N, int K)
{
    const float* A = (SEL == 0) ? g_m : (SEL == 1) ? g_fc1 : g_fc2;
    float* C = (SEL == 0) ? g_fc1 : (SEL == 1) ? g_fc2 : outp;

    __shared__ float As[8][64];
    __shared__ float Bs[8][64];
    int n0 = blockIdx.x * 64;
    int m0 = blockIdx.y * 64;
    int tid = threadIdx.x;
    int tx = tid & 15;
    int ty = tid >> 4;

    float acc[4][4];
    #pragma unroll
    for (int i = 0; i < 4; i++)
        #pragma unroll
        for (int j = 0; j < 4; j++) acc[i][j] = 0.f;

    for (int k0 = 0; k0 < K; k0 += 8) {
        __syncthreads();
        #pragma unroll
        for (int l = 0; l < 2; l++) {
            int e = tid + l * 256;
            int r = e >> 3;
            int kk = e & 7;
            As[kk][r] = A[(m0 + r) * K + k0 + kk];
            int n = n0 + r;
            Bs[kk][r] = (n < N) ? Wt[n * K + k0 + kk] : 0.f;
        }
        __syncthreads();
        #pragma unroll
        for (int kk = 0; kk < 8; kk++) {
            float4 a4 = *(const float4*)&As[kk][ty * 4];
            float4 b4 = *(const float4*)&Bs[kk][tx * 4];
            float a[4] = {a4.x, a4.y, a4.z, a4.w};
            float bb[4] = {b4.x, b4.y, b4.z, b4.w};
            #pragma unroll
            for (int i = 0; i < 4; i++)
                #pragma unroll
                for (int j = 0; j < 4; j++) acc[i][j] += a[i] * bb[j];
        }
    }

    #pragma unroll
    for (int i = 0; i < 4; i++) {
        int m = m0 + ty * 4 + i;
        #pragma unroll
        for (int j = 0; j < 4; j++) {
            int n = n0 + tx * 4 + j;
            if (n < N) {
                float v = acc[i][j] + bias[n];
                if (ACT == 0) v = fmaxf(v, 0.f);
                else v = 1.f / (1.f + __expf(-v));
                C[m * N + n] = v;
            }
        }
    }
}

// ---------------------------------------------------------------------------
// probs: softmax over capsule norms. thread per image.
// ---------------------------------------------------------------------------
__global__ void probs_kernel(float* __restrict__ out)
{
    int b = blockIdx.x * 128 + threadIdx.x;
    if (b < BATCH) {
        float nr[10];
        float mx = -1e30f;
        #pragma unroll
        for (int k = 0; k < 10; k++) {
            float n2 = 0.f;
            #pragma unroll
            for (int d = 0; d < 16; d++) {
                float v = g_v[b * 160 + k * 16 + d];
                n2 += v * v;
            }
            nr[k] = sqrtf(n2);
            mx = fmaxf(mx, nr[k]);
        }
        float sum = 0.f;
        #pragma unroll
        for (int k = 0; k < 10; k++) {
            nr[k] = __expf(nr[k] - mx);
            sum += nr[k];
        }
        float inv = 1.f / sum;
        #pragma unroll
        for (int k = 0; k < 10; k++) out[b * 10 + k] = nr[k] * inv;
    }
}

// ---------------------------------------------------------------------------
extern "C" void kernel_launch(void* const* d_in, const int* in_sizes, int n_in,
                              void* d_out, int out_size)
{
    const float* x       = (const float*)d_in[0];
    const float* labels  = (const float*)d_in[1];
    const float* conv1_w = (const float*)d_in[2];
    const float* conv1_b = (const float*)d_in[3];
    const float* pc_w    = (const float*)d_in[4];
    const float* pc_b    = (const float*)d_in[5];
    const float* W       = (const float*)d_in[6];
    const float* fc1_w   = (const float*)d_in[7];
    const float* fc1_b   = (const float*)d_in[8];
    const float* fc2_w   = (const float*)d_in[9];
    const float* fc2_b   = (const float*)d_in[10];
    const float* fc3_w   = (const float*)d_in[11];
    const float* fc3_b   = (const float*)d_in[12];
    float* out = (float*)d_out;

    conv1_kernel<<<dim3(BATCH, 4), 256>>>(x, conv1_w, conv1_b);
    pcconv_kernel<<<dim3(BATCH, 4), 384>>>(pc_w, pc_b);
    squash_h_kernel<<<BATCH, 256>>>();
    uhat_kernel<<<1152, 256>>>(W);
    routing0_kernel<<<BATCH, 160>>>();
    routing_iter_kernel<<<BATCH, 256>>>();
    routing_iter_kernel<<<BATCH, 256>>>();
    mask_kernel<<<320, 256>>>(labels);
    gemm_kernel<0, 0><<<dim3(8, 8), 256>>>(fc1_w, fc1_b, out, 512, 512, 160);
    gemm_kernel<0, 1><<<dim3(16, 8), 256>>>(fc2_w, fc2_b, out, 512, 1024, 512);
    gemm_kernel<1, 2><<<dim3(13, 8), 256>>>(fc3_w, fc3_b, out + 5120, 512, 784, 1024);
    probs_kernel<<<4, 128>>>(out);
}

// round 2
// speedup vs baseline: 1.0658x; 1.0658x over previous
#include <cuda_runtime.h>
#include <cuda_bf16.h>
#include <math.h>

// ---------------------------------------------------------------------------
// CapsNet forward. B=512.
//   conv1:  [512,1,28,28] -> relu -> [512,256,20,20]     (FFMA2 packed over oc)
//   pcconv: stride2 9x9  -> [512,256,6,6] (+bias)        (FFMA2 packed over oc)
//   squash over 1152 -> hT [512,1152,8]
//   u_hat[b,i,k,d] = sum_e W[i,k,d,e]*hT[b,i,e]  -> [512,1152,160]
//   routing x3 -> v [512,10,16]
//   decoder: mask -> fc1 relu -> fc2 relu -> fc3 sigmoid -> dec [512,784]
//   probs = softmax(||v||) [512,10]
// Output: [probs (512*10)] then [dec (512*784)]
// ---------------------------------------------------------------------------

#define BATCH 512

__device__ float g_conv1[BATCH * 256 * 20 * 20];
__device__ float g_pc[BATCH * 256 * 36];
__device__ float g_hT[BATCH * 1152 * 8];
__device__ float g_uhat[BATCH * 1152 * 160];
__device__ float g_blog[BATCH * 1152 * 10];
__device__ float g_v[BATCH * 160];
__device__ float g_m[BATCH * 160];
__device__ float g_fc1[BATCH * 512];
__device__ float g_fc2[BATCH * 1024];

// packed fp32x2 helpers (Blackwell paired-FMA path; scalar FFMA is half-rate)
__device__ __forceinline__ void ffma2(unsigned long long& d,
                                      unsigned long long a,
                                      unsigned long long b) {
    asm("fma.rn.f32x2 %0, %1, %2, %0;" : "+l"(d) : "l"(a), "l"(b));
}
__device__ __forceinline__ unsigned long long pack2(float v) {
    unsigned long long r;
    asm("mov.b64 %0, {%1, %2};" : "=l"(r) : "f"(v), "f"(v));
    return r;
}
__device__ __forceinline__ void unpack2(unsigned long long p, float& lo, float& hi) {
    asm("mov.b64 {%0, %1}, %2;" : "=f"(lo), "=f"(hi) : "l"(p));
}

#define CW 68  // padded smem row stride (words) for transposed weight tiles

// ---------------------------------------------------------------------------
// conv1: 1->256, 9x9, valid, relu.  grid (512, 4), block 128.
// thread = (ocp in [0,32) -> 2 oc, yg in [0,4) -> 5 rows). FFMA2 over oc pair.
// ---------------------------------------------------------------------------
__global__ __launch_bounds__(128, 4) void conv1_kernel(
    const float* __restrict__ x, const float* __restrict__ w,
    const float* __restrict__ bias)
{
    int b = blockIdx.x;
    int ocg = blockIdx.y;
    __shared__ float s_img[784];
    __shared__ float s_w[81 * CW];  // [e][oc_l] transposed
    int tid = threadIdx.x;

    for (int i = tid; i < 196; i += 128)
        *(float4*)&s_img[i * 4] = *(const float4*)&x[b * 784 + i * 4];
    for (int i = tid; i < 64 * 81; i += 128) {
        int r = i / 81;
        int e = i - r * 81;
        s_w[e * CW + r] = w[(ocg * 64 + r) * 81 + e];
    }
    __syncthreads();

    int ocp = tid & 31;
    int yg = tid >> 5;
    int oc0 = ocg * 64 + ocp * 2;
    float bv0 = bias[oc0], bv1 = bias[oc0 + 1];

    for (int yi = 0; yi < 5; yi++) {
        int y = yg * 5 + yi;
        unsigned long long acc[20];
        #pragma unroll
        for (int xx = 0; xx < 20; xx++) acc[xx] = 0ull;

        for (int ky = 0; ky < 9; ky++) {
            const float* rowp = s_img + (y + ky) * 28;
            unsigned long long rp[28];
            #pragma unroll
            for (int q = 0; q < 7; q++) {
                float4 r4 = *(const float4*)(rowp + q * 4);
                rp[q * 4 + 0] = pack2(r4.x);
                rp[q * 4 + 1] = pack2(r4.y);
                rp[q * 4 + 2] = pack2(r4.z);
                rp[q * 4 + 3] = pack2(r4.w);
            }
            #pragma unroll
            for (int kx = 0; kx < 9; kx++) {
                unsigned long long wp =
                    *(const unsigned long long*)(s_w + (ky * 9 + kx) * CW + ocp * 2);
                #pragma unroll
                for (int xx = 0; xx < 20; xx++) ffma2(acc[xx], wp, rp[xx + kx]);
            }
        }
        float* o0 = g_conv1 + ((size_t)(b * 256 + oc0)) * 400 + y * 20;
        float* o1 = o0 + 400;
        #pragma unroll
        for (int xx = 0; xx < 20; xx++) {
            float lo, hi;
            unpack2(acc[xx], lo, hi);
            o0[xx] = fmaxf(lo + bv0, 0.f);
            o1[xx] = fmaxf(hi + bv1, 0.f);
        }
    }
}

// ---------------------------------------------------------------------------
// pcconv: 256->256, 9x9, stride 2.  grid (256, 4), block 96.
// Block: 2 images x 64 oc x all 36 outputs.
// thread = (ocq in [0,8) -> 8 oc, y in [0,6), bl in [0,2)).
// Weights staged transposed per single ic: s_w[e][oc_l], stride CW.
// Inner loop: 24 FFMA2 per kx (4 oc-pairs x 6 x), rin broadcast-packed.
// ---------------------------------------------------------------------------
__global__ __launch_bounds__(96, 5) void pcconv_kernel(
    const float* __restrict__ w, const float* __restrict__ bias)
{
    int bq = blockIdx.x;   // images bq*2 + {0,1}
    int ocg = blockIdx.y;  // 64-oc group
    __shared__ float s_in[2 * 400];
    __shared__ float s_w[81 * CW];
    int tid = threadIdx.x;
    int ocq = tid & 7;
    int y = (tid >> 3) % 6;
    int bl = tid / 48;

    unsigned long long acc[4][6];
    #pragma unroll
    for (int p = 0; p < 4; p++)
        #pragma unroll
        for (int xx = 0; xx < 6; xx++) acc[p][xx] = 0ull;

    const float* inb = g_conv1 + (size_t)(bq * 2) * 256 * 400;
    const float* wb = w + (size_t)(ocg * 64) * 20736;

    for (int ic = 0; ic < 256; ic++) {
        __syncthreads();
        for (int i = tid; i < 200; i += 96) {
            int img = i / 100;
            int j = (i - img * 100) * 4;
            *(float4*)&s_in[img * 400 + j] =
                *(const float4*)&inb[(size_t)(img * 256 + ic) * 400 + j];
        }
        for (int i = tid; i < 64 * 81; i += 96) {
            int r = i / 81;
            int e = i - r * 81;
            s_w[e * CW + r] = wb[(size_t)r * 20736 + ic * 81 + e];
        }
        __syncthreads();

        for (int ky = 0; ky < 9; ky++) {
            int ir = 2 * y + ky;
            const float* rowp = s_in + bl * 400 + ir * 20;
            unsigned long long rp[19];
            {
                float4 r0 = *(const float4*)(rowp + 0);
                float4 r1 = *(const float4*)(rowp + 4);
                float4 r2 = *(const float4*)(rowp + 8);
                float4 r3 = *(const float4*)(rowp + 12);
                float4 r4 = *(const float4*)(rowp + 16);
                rp[0] = pack2(r0.x);  rp[1] = pack2(r0.y);
                rp[2] = pack2(r0.z);  rp[3] = pack2(r0.w);
                rp[4] = pack2(r1.x);  rp[5] = pack2(r1.y);
                rp[6] = pack2(r1.z);  rp[7] = pack2(r1.w);
                rp[8] = pack2(r2.x);  rp[9] = pack2(r2.y);
                rp[10] = pack2(r2.z); rp[11] = pack2(r2.w);
                rp[12] = pack2(r3.x); rp[13] = pack2(r3.y);
                rp[14] = pack2(r3.z); rp[15] = pack2(r3.w);
                rp[16] = pack2(r4.x); rp[17] = pack2(r4.y);
                rp[18] = pack2(r4.z);
            }
            #pragma unroll
            for (int kx = 0; kx < 9; kx++) {
                const float* wp = s_w + (ky * 9 + kx) * CW + ocq * 8;
                ulonglong2 wA = *(const ulonglong2*)(wp);
                ulonglong2 wB = *(const ulonglong2*)(wp + 4);
                #pragma unroll
                for (int xx = 0; xx < 6; xx++) {
                    unsigned long long rv = rp[2 * xx + kx];
                    ffma2(acc[0][xx], wA.x, rv);
                    ffma2(acc[1][xx], wA.y, rv);
                    ffma2(acc[2][xx], wB.x, rv);
                    ffma2(acc[3][xx], wB.y, rv);
                }
            }
        }
    }

    int b = bq * 2 + bl;
    #pragma unroll
    for (int p = 0; p < 4; p++) {
        int oc = ocg * 64 + ocq * 8 + p * 2;
        float bv0 = bias[oc], bv1 = bias[oc + 1];
        float* o0 = g_pc + ((size_t)(b * 256 + oc) * 6 + y) * 6;
        float* o1 = o0 + 36;
        #pragma unroll
        for (int xx = 0; xx < 6; xx++) {
            float lo, hi;
            unpack2(acc[p][xx], lo, hi);
            o0[xx] = lo + bv0;
            o1[xx] = hi + bv1;
        }
    }
}

// ---------------------------------------------------------------------------
// squash over 1152 + transpose to hT[b,1152,8].  grid 512, block 256.
// ---------------------------------------------------------------------------
__global__ __launch_bounds__(256) void squash_h_kernel()
{
    int b = blockIdx.x;
    int tid = threadIdx.x;
    __shared__ float s_scale[8];
    int g = tid >> 5;
    int lane = tid & 31;
    const float* pb = g_pc + (size_t)b * 9216;

    float ss = 0.f;
    for (int j = lane; j < 1152; j += 32) {
        float v = pb[g * 1152 + j];
        ss += v * v;
    }
    #pragma unroll
    for (int o = 16; o; o >>= 1) ss += __shfl_xor_sync(0xffffffffu, ss, o);
    if (lane == 0) s_scale[g] = sqrtf(ss) / (1.f + ss);
    __syncthreads();

    for (int idx = tid; idx < 9216; idx += 256) {
        int c = idx / 36;
        int s = idx - c * 36;
        int g2 = c >> 5;
        int pos = ((c & 31) * 36) + s;
        g_hT[((size_t)b * 1152 + pos) * 8 + g2] = pb[idx] * s_scale[g2];
    }
}

// ---------------------------------------------------------------------------
// u_hat[b,i,kd] = sum_e W[i,kd,e]*hT[b,i,e].  grid 1152, block 256.
// ---------------------------------------------------------------------------
__global__ __launch_bounds__(256) void uhat_kernel(const float* __restrict__ W)
{
    int i = blockIdx.x;
    __shared__ float sW[1280];
    __shared__ float sh[32 * 8];
    int tid = threadIdx.x;
    for (int j = tid; j < 1280; j += 256)
        sW[(j & 7) * 160 + (j >> 3)] = W[(size_t)i * 1280 + j];

    for (int b0 = 0; b0 < BATCH; b0 += 32) {
        __syncthreads();
        sh[tid] = g_hT[((size_t)(b0 + (tid >> 3)) * 1152 + i) * 8 + (tid & 7)];
        __syncthreads();
        if (tid < 160) {
            #pragma unroll 4
            for (int bb = 0; bb < 32; bb++) {
                float u = 0.f;
                #pragma unroll
                for (int e = 0; e < 8; e++) u += sW[e * 160 + tid] * sh[bb * 8 + e];
                g_uhat[((size_t)(b0 + bb) * 1152 + i) * 160 + tid] = u;
            }
        }
    }
}

// ---------------------------------------------------------------------------
// routing iter 0: c = 1/10 -> s = 0.1*sum_i u; v = squash_d(s); zero b-logits.
// ---------------------------------------------------------------------------
__global__ __launch_bounds__(160) void routing0_kernel()
{
    int b = blockIdx.x;
    int t = threadIdx.x;
    for (int j = t; j < 11520; j += 160) g_blog[(size_t)b * 11520 + j] = 0.f;

    const float* ub = g_uhat + (size_t)b * 184320;
    float s0 = 0.f, s1 = 0.f, s2 = 0.f, s3 = 0.f;
    for (int i = 0; i < 1152; i += 4) {
        s0 += ub[(i + 0) * 160 + t];
        s1 += ub[(i + 1) * 160 + t];
        s2 += ub[(i + 2) * 160 + t];
        s3 += ub[(i + 3) * 160 + t];
    }
    float s = 0.1f * (s0 + s1 + s2 + s3);

    __shared__ float s_s[160];
    s_s[t] = s;
    __syncthreads();
    int k = t >> 4;
    float n2 = 0.f;
    #pragma unroll
    for (int d = 0; d < 16; d++) {
        float v = s_s[k * 16 + d];
        n2 += v * v;
    }
    g_v[b * 160 + t] = s * (sqrtf(n2) / (1.f + n2));
}

// ---------------------------------------------------------------------------
// routing iter (r=1,2). grid 512, block 256.
// ---------------------------------------------------------------------------
__global__ __launch_bounds__(256) void routing_iter_kernel()
{
    int b = blockIdx.x;
    int t = threadIdx.x;
    __shared__ float v_s[160];
    __shared__ float c_s[1152 * 10];
    __shared__ float s_s[160];

    if (t < 160) v_s[t] = g_v[b * 160 + t];
    __syncthreads();

    const float* ub = g_uhat + (size_t)b * 184320;
    float* blb = g_blog + (size_t)b * 11520;

    for (int i = t; i < 1152; i += 256) {
        const float4* u4 = (const float4*)(ub + i * 160);
        float bl[10];
        float mx = -1e30f;
        #pragma unroll
        for (int k = 0; k < 10; k++) {
            float dk = 0.f;
            #pragma unroll
            for (int j = 0; j < 4; j++) {
                float4 u = u4[k * 4 + j];
                dk += u.x * v_s[k * 16 + 4 * j + 0];
                dk += u.y * v_s[k * 16 + 4 * j + 1];
                dk += u.z * v_s[k * 16 + 4 * j + 2];
                dk += u.w * v_s[k * 16 + 4 * j + 3];
            }
            float nb = blb[i * 10 + k] + dk;
            blb[i * 10 + k] = nb;
            bl[k] = nb;
            mx = fmaxf(mx, nb);
        }
        float sum = 0.f;
        #pragma unroll
        for (int k = 0; k < 10; k++) {
            float e = __expf(bl[k] - mx);
            bl[k] = e;
            sum += e;
        }
        float inv = 1.f / sum;
        #pragma unroll
        for (int k = 0; k < 10; k++) c_s[i * 10 + k] = bl[k] * inv;
    }
    __syncthreads();

    float s = 0.f;
    if (t < 160) {
        int k = t >> 4;
        float p0 = 0.f, p1 = 0.f;
        for (int i = 0; i < 1152; i += 2) {
            p0 += c_s[(i + 0) * 10 + k] * __ldg(ub + (i + 0) * 160 + t);
            p1 += c_s[(i + 1) * 10 + k] * __ldg(ub + (i + 1) * 160 + t);
        }
        s = p0 + p1;
    }
    __syncthreads();
    if (t < 160) s_s[t] = s;
    __syncthreads();
    if (t < 160) {
        int k = t >> 4;
        float n2 = 0.f;
        #pragma unroll
        for (int d = 0; d < 16; d++) {
            float v = s_s[k * 16 + d];
            n2 += v * v;
        }
        g_v[b * 160 + t] = s * (sqrtf(n2) / (1.f + n2));
    }
}

// ---------------------------------------------------------------------------
__global__ void mask_kernel(const float* __restrict__ labels)
{
    int idx = blockIdx.x * 256 + threadIdx.x;
    if (idx < BATCH * 160) {
        int b = idx / 160;
        int k = (idx - b * 160) >> 4;
        g_m[idx] = g_v[idx] * labels[b * 10 + k];
    }
}

// ---------------------------------------------------------------------------
// GEMM: C[M,N] = act(A[M,K] @ Wt[N,K]^T + bias). 64x64 tile, BK=8.
// ---------------------------------------------------------------------------
template <int ACT, int SEL>
__global__ __launch_bounds__(256) void gemm_kernel(
    const float* __restrict__ Wt, const float* __restrict__ bias,
    float* __restrict__ outp, int M, int N, int K)
{
    const float* A = (SEL == 0) ? g_m : (SEL == 1) ? g_fc1 : g_fc2;
    float* C = (SEL == 0) ? g_fc1 : (SEL == 1) ? g_fc2 : outp;

    __shared__ float As[8][64];
    __shared__ float Bs[8][64];
    int n0 = blockIdx.x * 64;
    int m0 = blockIdx.y * 64;
    int tid = threadIdx.x;
    int tx = tid & 15;
    int ty = tid >> 4;

    float acc[4][4];
    #pragma unroll
    for (int i = 0; i < 4; i++)
        #pragma unroll
        for (int j = 0; j < 4; j++) acc[i][j] = 0.f;

    for (int k0 = 0; k0 < K; k0 += 8) {
        __syncthreads();
        #pragma unroll
        for (int l = 0; l < 2; l++) {
            int e = tid + l * 256;
            int r = e >> 3;
            int kk = e & 7;
            As[kk][r] = A[(m0 + r) * K + k0 + kk];
            int n = n0 + r;
            Bs[kk][r] = (n < N) ? Wt[n * K + k0 + kk] : 0.f;
        }
        __syncthreads();
        #pragma unroll
        for (int kk = 0; kk < 8; kk++) {
            float4 a4 = *(const float4*)&As[kk][ty * 4];
            float4 b4 = *(const float4*)&Bs[kk][tx * 4];
            float a[4] = {a4.x, a4.y, a4.z, a4.w};
            float bb[4] = {b4.x, b4.y, b4.z, b4.w};
            #pragma unroll
            for (int i = 0; i < 4; i++)
                #pragma unroll
                for (int j = 0; j < 4; j++) acc[i][j] += a[i] * bb[j];
        }
    }

    #pragma unroll
    for (int i = 0; i < 4; i++) {
        int m = m0 + ty * 4 + i;
        #pragma unroll
        for (int j = 0; j < 4; j++) {
            int n = n0 + tx * 4 + j;
            if (n < N) {
                float v = acc[i][j] + bias[n];
                if (ACT == 0) v = fmaxf(v, 0.f);
                else v = 1.f / (1.f + __expf(-v));
                C[m * N + n] = v;
            }
        }
    }
}

// ---------------------------------------------------------------------------
__global__ void probs_kernel(float* __restrict__ out)
{
    int b = blockIdx.x * 128 + threadIdx.x;
    if (b < BATCH) {
        float nr[10];
        float mx = -1e30f;
        #pragma unroll
        for (int k = 0; k < 10; k++) {
            float n2 = 0.f;
            #pragma unroll
            for (int d = 0; d < 16; d++) {
                float v = g_v[b * 160 + k * 16 + d];
                n2 += v * v;
            }
            nr[k] = sqrtf(n2);
            mx = fmaxf(mx, nr[k]);
        }
        float sum = 0.f;
        #pragma unroll
        for (int k = 0; k < 10; k++) {
            nr[k] = __expf(nr[k] - mx);
            sum += nr[k];
        }
        float inv = 1.f / sum;
        #pragma unroll
        for (int k = 0; k < 10; k++) out[b * 10 + k] = nr[k] * inv;
    }
}

// ---------------------------------------------------------------------------
extern "C" void kernel_launch(void* const* d_in, const int* in_sizes, int n_in,
                              void* d_out, int out_size)
{
    const float* x       = (const float*)d_in[0];
    const float* labels  = (const float*)d_in[1];
    const float* conv1_w = (const float*)d_in[2];
    const float* conv1_b = (const float*)d_in[3];
    const float* pc_w    = (const float*)d_in[4];
    const float* pc_b    = (const float*)d_in[5];
    const float* W       = (const float*)d_in[6];
    const float* fc1_w   = (const float*)d_in[7];
    const float* fc1_b   = (const float*)d_in[8];
    const float* fc2_w   = (const float*)d_in[9];
    const float* fc2_b   = (const float*)d_in[10];
    const float* fc3_w   = (const float*)d_in[11];
    const float* fc3_b   = (const float*)d_in[12];
    float* out = (float*)d_out;

    conv1_kernel<<<dim3(BATCH, 4), 128>>>(x, conv1_w, conv1_b);
    pcconv_kernel<<<dim3(256, 4), 96>>>(pc_w, pc_b);
    squash_h_kernel<<<BATCH, 256>>>();
    uhat_kernel<<<1152, 256>>>(W);
    routing0_kernel<<<BATCH, 160>>>();
    routing_iter_kernel<<<BATCH, 256>>>();
    routing_iter_kernel<<<BATCH, 256>>>();
    mask_kernel<<<320, 256>>>(labels);
    gemm_kernel<0, 0><<<dim3(8, 8), 256>>>(fc1_w, fc1_b, out, 512, 512, 160);
    gemm_kernel<0, 1><<<dim3(16, 8), 256>>>(fc2_w, fc2_b, out, 512, 1024, 512);
    gemm_kernel<1, 2><<<dim3(13, 8), 256>>>(fc3_w, fc3_b, out + 5120, 512, 784, 1024);
    probs_kernel<<<4, 128>>>(out);
}

// round 4
// speedup vs baseline: 3.1641x; 2.9688x over previous
#include <cuda_runtime.h>
#include <cuda_bf16.h>
#include <cstdint>
#include <math.h>

// ---------------------------------------------------------------------------
// CapsNet forward. B=512.
//   conv1:  [512,1,28,28] -> relu -> channel-last bf16 hi/lo [b,iy,ix,ic]
//   pcconv: mma.sync bf16-split implicit GEMM -> g_pc [512,256,36] (+bias)
//   squash over 1152 -> hT; u_hat; routing x3; decoder FCs; probs
// Output: [probs (512*10)] then [dec (512*784)]
// ---------------------------------------------------------------------------

#define BATCH 512

__device__ __nv_bfloat16 g_clhi[BATCH * 400 * 256];   // conv1 out hi, ch-last
__device__ __nv_bfloat16 g_cllo[BATCH * 400 * 256];   // conv1 out lo
__device__ __nv_bfloat16 g_wrhi[256 * 81 * 256];      // pc weights [oc][tap][ic] hi
__device__ __nv_bfloat16 g_wrlo[256 * 81 * 256];
__device__ float g_pc[BATCH * 256 * 36];
__device__ float g_hT[BATCH * 1152 * 8];
__device__ float g_uhat[BATCH * 1152 * 160];
__device__ float g_blog[BATCH * 1152 * 10];
__device__ float g_v[BATCH * 160];
__device__ float g_m[BATCH * 160];
__device__ float g_fc1[BATCH * 512];
__device__ float g_fc2[BATCH * 1024];

// ---------------- helpers ---------------------------------------------------
__device__ __forceinline__ uint32_t smem_u32(const void* p) {
    uint32_t a;
    asm("{ .reg .u64 t; cvta.to.shared.u64 t, %1; cvt.u32.u64 %0, t; }"
        : "=r"(a) : "l"(p));
    return a;
}
__device__ __forceinline__ void ldsm_x4(uint32_t& d0, uint32_t& d1,
                                        uint32_t& d2, uint32_t& d3,
                                        uint32_t addr) {
    asm volatile("ldmatrix.sync.aligned.m8n8.x4.shared.b16 {%0,%1,%2,%3}, [%4];"
                 : "=r"(d0), "=r"(d1), "=r"(d2), "=r"(d3) : "r"(addr));
}
__device__ __forceinline__ void mma16816(float* c, const uint32_t* a,
                                         const uint32_t* b) {
    asm volatile(
        "mma.sync.aligned.m16n8k16.row.col.f32.bf16.bf16.f32 "
        "{%0,%1,%2,%3}, {%4,%5,%6,%7}, {%8,%9}, {%0,%1,%2,%3};"
        : "+f"(c[0]), "+f"(c[1]), "+f"(c[2]), "+f"(c[3])
        : "r"(a[0]), "r"(a[1]), "r"(a[2]), "r"(a[3]), "r"(b[0]), "r"(b[1]));
}
#define SW128(o) ((o) ^ (((o) >> 3) & 0x70))

// packed fp32x2 helpers for conv1
__device__ __forceinline__ void ffma2(unsigned long long& d,
                                      unsigned long long a,
                                      unsigned long long b) {
    asm("fma.rn.f32x2 %0, %1, %2, %0;" : "+l"(d) : "l"(a), "l"(b));
}
__device__ __forceinline__ unsigned long long pack2(float v) {
    unsigned long long r;
    asm("mov.b64 %0, {%1, %2};" : "=l"(r) : "f"(v), "f"(v));
    return r;
}
__device__ __forceinline__ void unpack2(unsigned long long p, float& lo, float& hi) {
    asm("mov.b64 {%0, %1}, %2;" : "=f"(lo), "=f"(hi) : "l"(p));
}

#define CW 68

// ---------------------------------------------------------------------------
// conv1: 1->256, 9x9, valid, relu -> channel-last bf16 hi/lo.
// grid (512, 4), block 128.
// ---------------------------------------------------------------------------
__global__ __launch_bounds__(128, 4) void conv1_kernel(
    const float* __restrict__ x, const float* __restrict__ w,
    const float* __restrict__ bias)
{
    int b = blockIdx.x;
    int ocg = blockIdx.y;
    __shared__ float s_img[784];
    __shared__ float s_w[81 * CW];
    int tid = threadIdx.x;

    for (int i = tid; i < 196; i += 128)
        *(float4*)&s_img[i * 4] = *(const float4*)&x[b * 784 + i * 4];
    for (int i = tid; i < 64 * 81; i += 128) {
        int r = i / 81;
        int e = i - r * 81;
        s_w[e * CW + r] = w[(ocg * 64 + r) * 81 + e];
    }
    __syncthreads();

    int ocp = tid & 31;
    int yg = tid >> 5;
    int oc0 = ocg * 64 + ocp * 2;
    float bv0 = bias[oc0], bv1 = bias[oc0 + 1];

    for (int yi = 0; yi < 5; yi++) {
        int y = yg * 5 + yi;
        unsigned long long acc[20];
        #pragma unroll
        for (int xx = 0; xx < 20; xx++) acc[xx] = 0ull;

        for (int ky = 0; ky < 9; ky++) {
            const float* rowp = s_img + (y + ky) * 28;
            unsigned long long rp[28];
            #pragma unroll
            for (int q = 0; q < 7; q++) {
                float4 r4 = *(const float4*)(rowp + q * 4);
                rp[q * 4 + 0] = pack2(r4.x);
                rp[q * 4 + 1] = pack2(r4.y);
                rp[q * 4 + 2] = pack2(r4.z);
                rp[q * 4 + 3] = pack2(r4.w);
            }
            #pragma unroll
            for (int kx = 0; kx < 9; kx++) {
                unsigned long long wp =
                    *(const unsigned long long*)(s_w + (ky * 9 + kx) * CW + ocp * 2);
                #pragma unroll
                for (int xx = 0; xx < 20; xx++) ffma2(acc[xx], wp, rp[xx + kx]);
            }
        }
        #pragma unroll
        for (int xx = 0; xx < 20; xx++) {
            float v0, v1;
            unpack2(acc[xx], v0, v1);
            v0 = fmaxf(v0 + bv0, 0.f);
            v1 = fmaxf(v1 + bv1, 0.f);
            __nv_bfloat16 h0 = __float2bfloat16(v0);
            __nv_bfloat16 h1 = __float2bfloat16(v1);
            __nv_bfloat16 l0 = __float2bfloat16(v0 - __bfloat162float(h0));
            __nv_bfloat16 l1 = __float2bfloat16(v1 - __bfloat162float(h1));
            int idx32 = ((b * 20 + y) * 20 + xx) * 128 + ocg * 32 + ocp;
            __nv_bfloat162 h2; h2.x = h0; h2.y = h1;
            __nv_bfloat162 l2; l2.x = l0; l2.y = l1;
            ((__nv_bfloat162*)g_clhi)[idx32] = h2;
            ((__nv_bfloat162*)g_cllo)[idx32] = l2;
        }
    }
}

// ---------------------------------------------------------------------------
// weight relayout: pc_w [oc][ic][81] -> g_wr{hi,lo} [oc][tap][ic] bf16
// ---------------------------------------------------------------------------
__global__ __launch_bounds__(256) void wrelayout_kernel(const float* __restrict__ w)
{
    int oc = blockIdx.x;
    int ic = threadIdx.x;
    const float* src = w + ((size_t)oc * 256 + ic) * 81;
    for (int e = 0; e < 81; e++) {
        float v = src[e];
        __nv_bfloat16 h = __float2bfloat16(v);
        __nv_bfloat16 l = __float2bfloat16(v - __bfloat162float(h));
        int di = (oc * 81 + e) * 256 + ic;
        g_wrhi[di] = h;
        g_wrlo[di] = l;
    }
}

// ---------------------------------------------------------------------------
// pcconv as mma.sync bf16-split implicit GEMM.
// grid (144, 2), block 256 (8 warps, 4(M) x 2(N)). Per CTA: M=128 npos,
// N=128 oc. K = 81 taps x 256 ic, chunked 64. smem stage 64KB, SW128.
// C = Ah*Bh + Ah*Bl + Al*Bh (fp32 acc) -> residual ~2^-18.
// ---------------------------------------------------------------------------
#define SM_AH 0
#define SM_AL 16384
#define SM_BH 32768
#define SM_BL 49152
#define PCG_SMEM 65536

__global__ __launch_bounds__(256, 2) void pcgemm_kernel(const float* __restrict__ bias)
{
    extern __shared__ char sm[];
    __shared__ int s_rowbase[128];

    int tid = threadIdx.x;
    int wid = tid >> 5;
    int lane = tid & 31;
    int warp_m = wid & 3;
    int warp_n = wid >> 2;
    int m0 = blockIdx.x * 128;
    int n0 = blockIdx.y * 128;
    uint32_t smbase = smem_u32(sm);

    if (tid < 128) {
        int npos = m0 + tid;
        int b = npos / 36;
        int pos = npos - b * 36;
        int y = pos / 6;
        int xq = pos - y * 6;
        s_rowbase[tid] = ((b * 20 + 2 * y) * 20 + 2 * xq) * 256;
    }

    float acc[2][8][4];
    #pragma unroll
    for (int i = 0; i < 2; i++)
        #pragma unroll
        for (int j = 0; j < 8; j++)
            #pragma unroll
            for (int k = 0; k < 4; k++) acc[i][j][k] = 0.f;

    // per-lane ldmatrix address components (SW128 folds to kb ^ ((row&7)<<4))
    uint32_t swz = (uint32_t)(lane & 7) << 4;
    uint32_t a_row = smbase + SM_AH + (uint32_t)(warp_m * 32 + (lane & 15)) * 128;
    uint32_t akb = (uint32_t)(lane >> 4) << 4;                 // 0 / 16
    uint32_t b_row = smbase + SM_BH +
        (uint32_t)(warp_n * 64 + (lane & 7) + ((lane >> 4) & 1) * 8) * 128;
    uint32_t bkb = (uint32_t)((lane >> 3) & 1) << 4;           // 0 / 16

    int rr = tid >> 3;        // fill: row (0..31) + s*32
    int cc = tid & 7;         // fill: 16B column

    for (int kc = 0; kc < 324; kc++) {
        int kykx = kc >> 2;
        int ic0 = (kc & 3) << 6;
        int ky = kykx / 9;
        int kx = kykx - ky * 9;
        int aoff = (ky * 20 + kx) * 256 + ic0 + cc * 8;

        __syncthreads();
        #pragma unroll
        for (int s = 0; s < 4; s++) {
            int row = rr + s * 32;
            uint32_t off = SW128((uint32_t)(row * 128 + cc * 16));
            int ga = s_rowbase[row] + aoff;
            *(uint4*)(sm + SM_AH + off) = *(const uint4*)(g_clhi + ga);
            *(uint4*)(sm + SM_AL + off) = *(const uint4*)(g_cllo + ga);
            int gb = ((n0 + row) * 81 + kykx) * 256 + ic0 + cc * 8;
            *(uint4*)(sm + SM_BH + off) = *(const uint4*)(g_wrhi + gb);
            *(uint4*)(sm + SM_BL + off) = *(const uint4*)(g_wrlo + gb);
        }
        __syncthreads();

        #pragma unroll
        for (int j = 0; j < 4; j++) {
            uint32_t ka = ((uint32_t)(j * 32) + akb) ^ swz;
            uint32_t ah[8], al[8];
            ldsm_x4(ah[0], ah[1], ah[2], ah[3], a_row + ka);
            ldsm_x4(ah[4], ah[5], ah[6], ah[7], a_row + 2048 + ka);
            ldsm_x4(al[0], al[1], al[2], al[3], a_row + 16384 + ka);
            ldsm_x4(al[4], al[5], al[6], al[7], a_row + 16384 + 2048 + ka);
            uint32_t kb = ((uint32_t)(j * 32) + bkb) ^ swz;
            #pragma unroll
            for (int half = 0; half < 2; half++) {
                uint32_t bb = b_row + half * 4096;
                uint32_t bh[8], bl[8];
                ldsm_x4(bh[0], bh[1], bh[2], bh[3], bb + kb);
                ldsm_x4(bh[4], bh[5], bh[6], bh[7], bb + 2048 + kb);
                ldsm_x4(bl[0], bl[1], bl[2], bl[3], bb + 16384 + kb);
                ldsm_x4(bl[4], bl[5], bl[6], bl[7], bb + 16384 + 2048 + kb);
                #pragma unroll
                for (int tn = 0; tn < 4; tn++) {
                    #pragma unroll
                    for (int tm = 0; tm < 2; tm++) {
                        float* c = acc[tm][half * 4 + tn];
                        mma16816(c, &ah[4 * tm], &bh[2 * tn]);
                        mma16816(c, &ah[4 * tm], &bl[2 * tn]);
                        mma16816(c, &al[4 * tm], &bh[2 * tn]);
                    }
                }
            }
        }
    }

    // epilogue: acc -> g_pc[b*9216 + oc*36 + pos] (+bias)
    int r_in8 = lane >> 2;
    int c_in8 = (lane & 3) * 2;
    #pragma unroll
    for (int tm = 0; tm < 2; tm++) {
        int row0 = m0 + warp_m * 32 + tm * 16 + r_in8;
        int b0i = row0 / 36, p0i = row0 - b0i * 36;
        int row1 = row0 + 8;
        int b1i = row1 / 36, p1i = row1 - b1i * 36;
        #pragma unroll
        for (int tn = 0; tn < 8; tn++) {
            int col = n0 + warp_n * 64 + tn * 8 + c_in8;
            float bv0 = __ldg(bias + col);
            float bv1 = __ldg(bias + col + 1);
            const float* c = acc[tm][tn];
            g_pc[b0i * 9216 + col * 36 + p0i] = c[0] + bv0;
            g_pc[b0i * 9216 + (col + 1) * 36 + p0i] = c[1] + bv1;
            g_pc[b1i * 9216 + col * 36 + p1i] = c[2] + bv0;
            g_pc[b1i * 9216 + (col + 1) * 36 + p1i] = c[3] + bv1;
        }
    }
}

// ---------------------------------------------------------------------------
// squash over 1152 + transpose to hT[b,1152,8].  grid 512, block 256.
// ---------------------------------------------------------------------------
__global__ __launch_bounds__(256) void squash_h_kernel()
{
    int b = blockIdx.x;
    int tid = threadIdx.x;
    __shared__ float s_scale[8];
    int g = tid >> 5;
    int lane = tid & 31;
    const float* pb = g_pc + (size_t)b * 9216;

    float ss = 0.f;
    for (int j = lane; j < 1152; j += 32) {
        float v = pb[g * 1152 + j];
        ss += v * v;
    }
    #pragma unroll
    for (int o = 16; o; o >>= 1) ss += __shfl_xor_sync(0xffffffffu, ss, o);
    if (lane == 0) s_scale[g] = sqrtf(ss) / (1.f + ss);
    __syncthreads();

    for (int idx = tid; idx < 9216; idx += 256) {
        int c = idx / 36;
        int s = idx - c * 36;
        int g2 = c >> 5;
        int pos = ((c & 31) * 36) + s;
        g_hT[((size_t)b * 1152 + pos) * 8 + g2] = pb[idx] * s_scale[g2];
    }
}

// ---------------------------------------------------------------------------
// u_hat[b,i,kd] = sum_e W[i,kd,e]*hT[b,i,e].  grid 1152, block 256.
// ---------------------------------------------------------------------------
__global__ __launch_bounds__(256) void uhat_kernel(const float* __restrict__ W)
{
    int i = blockIdx.x;
    __shared__ float sW[1280];
    __shared__ float sh[32 * 8];
    int tid = threadIdx.x;
    for (int j = tid; j < 1280; j += 256)
        sW[(j & 7) * 160 + (j >> 3)] = W[(size_t)i * 1280 + j];

    for (int b0 = 0; b0 < BATCH; b0 += 32) {
        __syncthreads();
        sh[tid] = g_hT[((size_t)(b0 + (tid >> 3)) * 1152 + i) * 8 + (tid & 7)];
        __syncthreads();
        if (tid < 160) {
            #pragma unroll 4
            for (int bb = 0; bb < 32; bb++) {
                float u = 0.f;
                #pragma unroll
                for (int e = 0; e < 8; e++) u += sW[e * 160 + tid] * sh[bb * 8 + e];
                g_uhat[((size_t)(b0 + bb) * 1152 + i) * 160 + tid] = u;
            }
        }
    }
}

// ---------------------------------------------------------------------------
__global__ __launch_bounds__(160) void routing0_kernel()
{
    int b = blockIdx.x;
    int t = threadIdx.x;
    for (int j = t; j < 11520; j += 160) g_blog[(size_t)b * 11520 + j] = 0.f;

    const float* ub = g_uhat + (size_t)b * 184320;
    float s0 = 0.f, s1 = 0.f, s2 = 0.f, s3 = 0.f;
    for (int i = 0; i < 1152; i += 4) {
        s0 += ub[(i + 0) * 160 + t];
        s1 += ub[(i + 1) * 160 + t];
        s2 += ub[(i + 2) * 160 + t];
        s3 += ub[(i + 3) * 160 + t];
    }
    float s = 0.1f * (s0 + s1 + s2 + s3);

    __shared__ float s_s[160];
    s_s[t] = s;
    __syncthreads();
    int k = t >> 4;
    float n2 = 0.f;
    #pragma unroll
    for (int d = 0; d < 16; d++) {
        float v = s_s[k * 16 + d];
        n2 += v * v;
    }
    g_v[b * 160 + t] = s * (sqrtf(n2) / (1.f + n2));
}

// ---------------------------------------------------------------------------
__global__ __launch_bounds__(256) void routing_iter_kernel()
{
    int b = blockIdx.x;
    int t = threadIdx.x;
    __shared__ float v_s[160];
    __shared__ float c_s[1152 * 10];
    __shared__ float s_s[160];

    if (t < 160) v_s[t] = g_v[b * 160 + t];
    __syncthreads();

    const float* ub = g_uhat + (size_t)b * 184320;
    float* blb = g_blog + (size_t)b * 11520;

    for (int i = t; i < 1152; i += 256) {
        const float4* u4 = (const float4*)(ub + i * 160);
        float bl[10];
        float mx = -1e30f;
        #pragma unroll
        for (int k = 0; k < 10; k++) {
            float dk = 0.f;
            #pragma unroll
            for (int j = 0; j < 4; j++) {
                float4 u = u4[k * 4 + j];
                dk += u.x * v_s[k * 16 + 4 * j + 0];
                dk += u.y * v_s[k * 16 + 4 * j + 1];
                dk += u.z * v_s[k * 16 + 4 * j + 2];
                dk += u.w * v_s[k * 16 + 4 * j + 3];
            }
            float nb = blb[i * 10 + k] + dk;
            blb[i * 10 + k] = nb;
            bl[k] = nb;
            mx = fmaxf(mx, nb);
        }
        float sum = 0.f;
        #pragma unroll
        for (int k = 0; k < 10; k++) {
            float e = __expf(bl[k] - mx);
            bl[k] = e;
            sum += e;
        }
        float inv = 1.f / sum;
        #pragma unroll
        for (int k = 0; k < 10; k++) c_s[i * 10 + k] = bl[k] * inv;
    }
    __syncthreads();

    float s = 0.f;
    if (t < 160) {
        int k = t >> 4;
        float p0 = 0.f, p1 = 0.f;
        for (int i = 0; i < 1152; i += 2) {
            p0 += c_s[(i + 0) * 10 + k] * __ldg(ub + (i + 0) * 160 + t);
            p1 += c_s[(i + 1) * 10 + k] * __ldg(ub + (i + 1) * 160 + t);
        }
        s = p0 + p1;
    }
    __syncthreads();
    if (t < 160) s_s[t] = s;
    __syncthreads();
    if (t < 160) {
        int k = t >> 4;
        float n2 = 0.f;
        #pragma unroll
        for (int d = 0; d < 16; d++) {
            float v = s_s[k * 16 + d];
            n2 += v * v;
        }
        g_v[b * 160 + t] = s * (sqrtf(n2) / (1.f + n2));
    }
}

// ---------------------------------------------------------------------------
__global__ void mask_kernel(const float* __restrict__ labels)
{
    int idx = blockIdx.x * 256 + threadIdx.x;
    if (idx < BATCH * 160) {
        int b = idx / 160;
        int k = (idx - b * 160) >> 4;
        g_m[idx] = g_v[idx] * labels[b * 10 + k];
    }
}

// ---------------------------------------------------------------------------
template <int ACT, int SEL>
__global__ __launch_bounds__(256) void gemm_kernel(
    const float* __restrict__ Wt, const float* __restrict__ bias,
    float* __restrict__ outp, int M, int N, int K)
{
    const float* A = (SEL == 0) ? g_m : (SEL == 1) ? g_fc1 : g_fc2;
    float* C = (SEL == 0) ? g_fc1 : (SEL == 1) ? g_fc2 : outp;

    __shared__ float As[8][64];
    __shared__ float Bs[8][64];
    int n0 = blockIdx.x * 64;
    int m0 = blockIdx.y * 64;
    int tid = threadIdx.x;
    int tx = tid & 15;
    int ty = tid >> 4;

    float acc[4][4];
    #pragma unroll
    for (int i = 0; i < 4; i++)
        #pragma unroll
        for (int j = 0; j < 4; j++) acc[i][j] = 0.f;

    for (int k0 = 0; k0 < K; k0 += 8) {
        __syncthreads();
        #pragma unroll
        for (int l = 0; l < 2; l++) {
            int e = tid + l * 256;
            int r = e >> 3;
            int kk = e & 7;
            As[kk][r] = A[(m0 + r) * K + k0 + kk];
            int n = n0 + r;
            Bs[kk][r] = (n < N) ? Wt[n * K + k0 + kk] : 0.f;
        }
        __syncthreads();
        #pragma unroll
        for (int kk = 0; kk < 8; kk++) {
            float4 a4 = *(const float4*)&As[kk][ty * 4];
            float4 b4 = *(const float4*)&Bs[kk][tx * 4];
            float a[4] = {a4.x, a4.y, a4.z, a4.w};
            float bb[4] = {b4.x, b4.y, b4.z, b4.w};
            #pragma unroll
            for (int i = 0; i < 4; i++)
                #pragma unroll
                for (int j = 0; j < 4; j++) acc[i][j] += a[i] * bb[j];
        }
    }

    #pragma unroll
    for (int i = 0; i < 4; i++) {
        int m = m0 + ty * 4 + i;
        #pragma unroll
        for (int j = 0; j < 4; j++) {
            int n = n0 + tx * 4 + j;
            if (n < N) {
                float v = acc[i][j] + bias[n];
                if (ACT == 0) v = fmaxf(v, 0.f);
                else v = 1.f / (1.f + __expf(-v));
                C[m * N + n] = v;
            }
        }
    }
}

// ---------------------------------------------------------------------------
__global__ void probs_kernel(float* __restrict__ out)
{
    int b = blockIdx.x * 128 + threadIdx.x;
    if (b < BATCH) {
        float nr[10];
        float mx = -1e30f;
        #pragma unroll
        for (int k = 0; k < 10; k++) {
            float n2 = 0.f;
            #pragma unroll
            for (int d = 0; d < 16; d++) {
                float v = g_v[b * 160 + k * 16 + d];
                n2 += v * v;
            }
            nr[k] = sqrtf(n2);
            mx = fmaxf(mx, nr[k]);
        }
        float sum = 0.f;
        #pragma unroll
        for (int k = 0; k < 10; k++) {
            nr[k] = __expf(nr[k] - mx);
            sum += nr[k];
        }
        float inv = 1.f / sum;
        #pragma unroll
        for (int k = 0; k < 10; k++) out[b * 10 + k] = nr[k] * inv;
    }
}

// ---------------------------------------------------------------------------
extern "C" void kernel_launch(void* const* d_in, const int* in_sizes, int n_in,
                              void* d_out, int out_size)
{
    const float* x       = (const float*)d_in[0];
    const float* labels  = (const float*)d_in[1];
    const float* conv1_w = (const float*)d_in[2];
    const float* conv1_b = (const float*)d_in[3];
    const float* pc_w    = (const float*)d_in[4];
    const float* pc_b    = (const float*)d_in[5];
    const float* W       = (const float*)d_in[6];
    const float* fc1_w   = (const float*)d_in[7];
    const float* fc1_b   = (const float*)d_in[8];
    const float* fc2_w   = (const float*)d_in[9];
    const float* fc2_b   = (const float*)d_in[10];
    const float* fc3_w   = (const float*)d_in[11];
    const float* fc3_b   = (const float*)d_in[12];
    float* out = (float*)d_out;

    cudaFuncSetAttribute(pcgemm_kernel,
                         cudaFuncAttributeMaxDynamicSharedMemorySize, PCG_SMEM);

    conv1_kernel<<<dim3(BATCH, 4), 128>>>(x, conv1_w, conv1_b);
    wrelayout_kernel<<<256, 256>>>(pc_w);
    pcgemm_kernel<<<dim3(144, 2), 256, PCG_SMEM>>>(pc_b);
    squash_h_kernel<<<BATCH, 256>>>();
    uhat_kernel<<<1152, 256>>>(W);
    routing0_kernel<<<BATCH, 160>>>();
    routing_iter_kernel<<<BATCH, 256>>>();
    routing_iter_kernel<<<BATCH, 256>>>();
    mask_kernel<<<320, 256>>>(labels);
    gemm_kernel<0, 0><<<dim3(8, 8), 256>>>(fc1_w, fc1_b, out, 512, 512, 160);
    gemm_kernel<0, 1><<<dim3(16, 8), 256>>>(fc2_w, fc2_b, out, 512, 1024, 512);
    gemm_kernel<1, 2><<<dim3(13, 8), 256>>>(fc3_w, fc3_b, out + 5120, 512, 784, 1024);
    probs_kernel<<<4, 128>>>(out);
}

// round 5
// speedup vs baseline: 3.5440x; 1.1201x over previous
#include <cuda_runtime.h>
#include <cuda_bf16.h>
#include <cuda_fp16.h>
#include <cstdint>
#include <math.h>

// ---------------------------------------------------------------------------
// CapsNet forward. B=512.
//   conv1:  [512,1,28,28] -> relu -> channel-last bf16 hi/lo [b,iy,ix,ic]
//   pcconv: mma.sync bf16-split implicit GEMM (cp.async 2-stage, N=256/CTA)
//   squash over 1152 -> hT; u_hat (fp16 storage); routing x3; decoder; probs
// Output: [probs (512*10)] then [dec (512*784)]
// ---------------------------------------------------------------------------

#define BATCH 512

__device__ __nv_bfloat16 g_clhi[BATCH * 400 * 256];
__device__ __nv_bfloat16 g_cllo[BATCH * 400 * 256];
__device__ __nv_bfloat16 g_wrhi[256 * 81 * 256];   // [oc][tap][ic]
__device__ __nv_bfloat16 g_wrlo[256 * 81 * 256];
__device__ float g_pc[BATCH * 256 * 36];
__device__ float g_hT[BATCH * 1152 * 8];
__device__ __half g_uhat[BATCH * 1152 * 160];      // fp16 storage
__device__ float g_blog[BATCH * 1152 * 10];
__device__ float g_v[BATCH * 160];
__device__ float g_m[BATCH * 160];
__device__ float g_fc1[BATCH * 512];
__device__ float g_fc2[BATCH * 1024];

// ---------------- helpers ---------------------------------------------------
__device__ __forceinline__ uint32_t smem_u32(const void* p) {
    uint32_t a;
    asm("{ .reg .u64 t; cvta.to.shared.u64 t, %1; cvt.u32.u64 %0, t; }"
        : "=r"(a) : "l"(p));
    return a;
}
__device__ __forceinline__ void ldsm_x4(uint32_t& d0, uint32_t& d1,
                                        uint32_t& d2, uint32_t& d3,
                                        uint32_t addr) {
    asm volatile("ldmatrix.sync.aligned.m8n8.x4.shared.b16 {%0,%1,%2,%3}, [%4];"
                 : "=r"(d0), "=r"(d1), "=r"(d2), "=r"(d3) : "r"(addr));
}
__device__ __forceinline__ void mma16816(float* c, const uint32_t* a,
                                         const uint32_t* b) {
    asm volatile(
        "mma.sync.aligned.m16n8k16.row.col.f32.bf16.bf16.f32 "
        "{%0,%1,%2,%3}, {%4,%5,%6,%7}, {%8,%9}, {%0,%1,%2,%3};"
        : "+f"(c[0]), "+f"(c[1]), "+f"(c[2]), "+f"(c[3])
        : "r"(a[0]), "r"(a[1]), "r"(a[2]), "r"(a[3]), "r"(b[0]), "r"(b[1]));
}
#define CP16(dst, src) \
    asm volatile("cp.async.cg.shared.global [%0], [%1], 16;" \
                 :: "r"(dst), "l"(src) : "memory")
#define CP_COMMIT() asm volatile("cp.async.commit_group;" ::: "memory")
#define CP_WAIT1() asm volatile("cp.async.wait_group 1;" ::: "memory")
#define CP_WAIT0() asm volatile("cp.async.wait_group 0;" ::: "memory")

// fp32x2 helpers for conv1
__device__ __forceinline__ void ffma2(unsigned long long& d,
                                      unsigned long long a,
                                      unsigned long long b) {
    asm("fma.rn.f32x2 %0, %1, %2, %0;" : "+l"(d) : "l"(a), "l"(b));
}
__device__ __forceinline__ unsigned long long pack2(float v) {
    unsigned long long r;
    asm("mov.b64 %0, {%1, %2};" : "=l"(r) : "f"(v), "f"(v));
    return r;
}
__device__ __forceinline__ void unpack2(unsigned long long p, float& lo, float& hi) {
    asm("mov.b64 {%0, %1}, %2;" : "=f"(lo), "=f"(hi) : "l"(p));
}

#define CW 68

// ---------------------------------------------------------------------------
// conv1: 1->256, 9x9, valid, relu -> channel-last bf16 hi/lo. grid (512,4).
// ---------------------------------------------------------------------------
__global__ __launch_bounds__(128, 4) void conv1_kernel(
    const float* __restrict__ x, const float* __restrict__ w,
    const float* __restrict__ bias)
{
    int b = blockIdx.x;
    int ocg = blockIdx.y;
    __shared__ float s_img[784];
    __shared__ float s_w[81 * CW];
    int tid = threadIdx.x;

    for (int i = tid; i < 196; i += 128)
        *(float4*)&s_img[i * 4] = *(const float4*)&x[b * 784 + i * 4];
    for (int i = tid; i < 64 * 81; i += 128) {
        int r = i / 81;
        int e = i - r * 81;
        s_w[e * CW + r] = w[(ocg * 64 + r) * 81 + e];
    }
    __syncthreads();

    int ocp = tid & 31;
    int yg = tid >> 5;
    int oc0 = ocg * 64 + ocp * 2;
    float bv0 = bias[oc0], bv1 = bias[oc0 + 1];

    for (int yi = 0; yi < 5; yi++) {
        int y = yg * 5 + yi;
        unsigned long long acc[20];
        #pragma unroll
        for (int xx = 0; xx < 20; xx++) acc[xx] = 0ull;

        for (int ky = 0; ky < 9; ky++) {
            const float* rowp = s_img + (y + ky) * 28;
            unsigned long long rp[28];
            #pragma unroll
            for (int q = 0; q < 7; q++) {
                float4 r4 = *(const float4*)(rowp + q * 4);
                rp[q * 4 + 0] = pack2(r4.x);
                rp[q * 4 + 1] = pack2(r4.y);
                rp[q * 4 + 2] = pack2(r4.z);
                rp[q * 4 + 3] = pack2(r4.w);
            }
            #pragma unroll
            for (int kx = 0; kx < 9; kx++) {
                unsigned long long wp =
                    *(const unsigned long long*)(s_w + (ky * 9 + kx) * CW + ocp * 2);
                #pragma unroll
                for (int xx = 0; xx < 20; xx++) ffma2(acc[xx], wp, rp[xx + kx]);
            }
        }
        #pragma unroll
        for (int xx = 0; xx < 20; xx++) {
            float v0, v1;
            unpack2(acc[xx], v0, v1);
            v0 = fmaxf(v0 + bv0, 0.f);
            v1 = fmaxf(v1 + bv1, 0.f);
            __nv_bfloat16 h0 = __float2bfloat16(v0);
            __nv_bfloat16 h1 = __float2bfloat16(v1);
            __nv_bfloat16 l0 = __float2bfloat16(v0 - __bfloat162float(h0));
            __nv_bfloat16 l1 = __float2bfloat16(v1 - __bfloat162float(h1));
            int idx32 = ((b * 20 + y) * 20 + xx) * 128 + ocg * 32 + ocp;
            __nv_bfloat162 h2; h2.x = h0; h2.y = h1;
            __nv_bfloat162 l2; l2.x = l0; l2.y = l1;
            ((__nv_bfloat162*)g_clhi)[idx32] = h2;
            ((__nv_bfloat162*)g_cllo)[idx32] = l2;
        }
    }
}

// ---------------------------------------------------------------------------
// weight relayout via smem transpose: coalesced reads + uint4 writes.
// grid 256 (oc), block 256. dynamic smem 83KB.
// ---------------------------------------------------------------------------
__global__ __launch_bounds__(256) void wrelayout_kernel(const float* __restrict__ w)
{
    extern __shared__ char wsm[];
    __nv_bfloat16* shi = (__nv_bfloat16*)wsm;
    __nv_bfloat16* slo = shi + 81 * 256;
    int oc = blockIdx.x;
    int tid = threadIdx.x;
    const float* src = w + (size_t)oc * 20736;

    for (int j = tid; j < 20736; j += 256) {
        float v = src[j];
        int ic = j / 81;
        int e = j - ic * 81;
        __nv_bfloat16 h = __float2bfloat16(v);
        __nv_bfloat16 l = __float2bfloat16(v - __bfloat162float(h));
        shi[e * 256 + ic] = h;
        slo[e * 256 + ic] = l;
    }
    __syncthreads();

    uint4* dh = (uint4*)(g_wrhi + (size_t)oc * 20736);
    uint4* dl = (uint4*)(g_wrlo + (size_t)oc * 20736);
    const uint4* s4h = (const uint4*)shi;
    const uint4* s4l = (const uint4*)slo;
    for (int j = tid; j < 2592; j += 256) {
        dh[j] = s4h[j];
        dl[j] = s4l[j];
    }
}

// ---------------------------------------------------------------------------
// pcconv: bf16-split implicit GEMM, cp.async 2-stage, M=128 x N=256 per CTA.
// grid 144, block 256 (8 warps 4(M)x2(N)). K = 81 taps x 4 ic-chunks of 64.
// ---------------------------------------------------------------------------
#define SM_AH 0
#define SM_AL 16384
#define SM_BH 32768
#define SM_BL 65536
#define STAGE 98304
#define PCG_SMEM (2 * STAGE)

__global__ __launch_bounds__(256, 1) void pcgemm_kernel(const float* __restrict__ bias)
{
    extern __shared__ char sm[];
    __shared__ int s_rowbase[128];

    int tid = threadIdx.x;
    int wid = tid >> 5;
    int lane = tid & 31;
    int warp_m = wid & 3;
    int warp_n = wid >> 2;
    int m0 = blockIdx.x * 128;
    uint32_t smb = smem_u32(sm);

    if (tid < 128) {
        int npos = m0 + tid;
        int b = npos / 36;
        int pos = npos - b * 36;
        int y = pos / 6;
        int xq = pos - y * 6;
        s_rowbase[tid] = ((b * 20 + 2 * y) * 20 + 2 * xq) * 256;
    }
    __syncthreads();

    // fill-side constants: 24 cp.async per thread per stage
    int r0 = tid >> 3;   // 0..31
    int c = tid & 7;
    uint32_t dbase = (uint32_t)(r0 * 128) + (uint32_t)((c * 16) ^ ((r0 & 7) << 4));
    int rb[4];
    #pragma unroll
    for (int i = 0; i < 4; i++) rb[i] = s_rowbase[r0 + 32 * i];
    int bbase0 = r0 * 20736;

#define PCG_ISSUE(K) do { \
    int _kykx = (K) >> 2; \
    int _ic0 = ((K) & 3) << 6; \
    int _ky = _kykx / 9; \
    int _kx = _kykx - _ky * 9; \
    int _asrc = (_ky * 20 + _kx) * 256 + _ic0 + c * 8; \
    int _bsrc = _kykx * 256 + _ic0 + c * 8; \
    uint32_t _st = smb + ((K) & 1) * STAGE; \
    _Pragma("unroll") \
    for (int _i = 0; _i < 4; _i++) { \
        CP16(_st + SM_AH + dbase + _i * 4096, g_clhi + rb[_i] + _asrc); \
        CP16(_st + SM_AL + dbase + _i * 4096, g_cllo + rb[_i] + _asrc); \
    } \
    _Pragma("unroll") \
    for (int _t = 0; _t < 8; _t++) { \
        int _bo = bbase0 + _t * 663552 + _bsrc; \
        CP16(_st + SM_BH + dbase + _t * 4096, g_wrhi + _bo); \
        CP16(_st + SM_BL + dbase + _t * 4096, g_wrlo + _bo); \
    } \
} while (0)

    float acc[2][16][4];
    #pragma unroll
    for (int i = 0; i < 2; i++)
        #pragma unroll
        for (int j = 0; j < 16; j++)
            #pragma unroll
            for (int k = 0; k < 4; k++) acc[i][j][k] = 0.f;

    uint32_t swz = (uint32_t)(lane & 7) << 4;
    uint32_t a_row_off = SM_AH + (uint32_t)(warp_m * 32 + (lane & 15)) * 128;
    uint32_t akb = (uint32_t)(lane >> 4) << 4;
    uint32_t b_row_off = SM_BH +
        (uint32_t)(warp_n * 128 + (lane & 7) + ((lane >> 4) & 1) * 8) * 128;
    uint32_t bkb = (uint32_t)((lane >> 3) & 1) << 4;

    PCG_ISSUE(0);
    CP_COMMIT();

    for (int kc = 0; kc < 324; kc++) {
        if (kc < 323) {
            PCG_ISSUE(kc + 1);
            CP_COMMIT();
            CP_WAIT1();
        } else {
            CP_WAIT0();
        }
        __syncthreads();

        uint32_t st = smb + (kc & 1) * STAGE;
        uint32_t a_row = st + a_row_off;
        uint32_t b_row = st + b_row_off;
        #pragma unroll
        for (int j = 0; j < 4; j++) {
            uint32_t ka = ((uint32_t)(j * 32) + akb) ^ swz;
            uint32_t ah[8], al[8];
            ldsm_x4(ah[0], ah[1], ah[2], ah[3], a_row + ka);
            ldsm_x4(ah[4], ah[5], ah[6], ah[7], a_row + 2048 + ka);
            ldsm_x4(al[0], al[1], al[2], al[3], a_row + 16384 + ka);
            ldsm_x4(al[4], al[5], al[6], al[7], a_row + 16384 + 2048 + ka);
            uint32_t kb = ((uint32_t)(j * 32) + bkb) ^ swz;
            #pragma unroll
            for (int h = 0; h < 2; h++) {
                uint32_t bh[16], bl[16];
                #pragma unroll
                for (int q = 0; q < 4; q++) {
                    uint32_t bt = b_row + (uint32_t)((h * 4 + q) * 2048) + kb;
                    ldsm_x4(bh[4 * q], bh[4 * q + 1], bh[4 * q + 2], bh[4 * q + 3], bt);
                    ldsm_x4(bl[4 * q], bl[4 * q + 1], bl[4 * q + 2], bl[4 * q + 3],
                            bt + 32768);
                }
                #pragma unroll
                for (int q = 0; q < 4; q++) {
                    #pragma unroll
                    for (int sub = 0; sub < 2; sub++) {
                        int nn = h * 8 + q * 2 + sub;
                        #pragma unroll
                        for (int tm = 0; tm < 2; tm++) {
                            float* cc2 = acc[tm][nn];
                            mma16816(cc2, &ah[4 * tm], &bh[4 * q + 2 * sub]);
                            mma16816(cc2, &ah[4 * tm], &bl[4 * q + 2 * sub]);
                            mma16816(cc2, &al[4 * tm], &bh[4 * q + 2 * sub]);
                        }
                    }
                }
            }
        }
        __syncthreads();
    }

    // epilogue
    int r_in8 = lane >> 2;
    int c_in8 = (lane & 3) * 2;
    #pragma unroll
    for (int tm = 0; tm < 2; tm++) {
        int row0 = m0 + warp_m * 32 + tm * 16 + r_in8;
        int b0i = row0 / 36, p0i = row0 - b0i * 36;
        int row1 = row0 + 8;
        int b1i = row1 / 36, p1i = row1 - b1i * 36;
        #pragma unroll
        for (int nn = 0; nn < 16; nn++) {
            int col = warp_n * 128 + nn * 8 + c_in8;
            float bv0 = __ldg(bias + col);
            float bv1 = __ldg(bias + col + 1);
            const float* cc2 = acc[tm][nn];
            g_pc[b0i * 9216 + col * 36 + p0i] = cc2[0] + bv0;
            g_pc[b0i * 9216 + (col + 1) * 36 + p0i] = cc2[1] + bv1;
            g_pc[b1i * 9216 + col * 36 + p1i] = cc2[2] + bv0;
            g_pc[b1i * 9216 + (col + 1) * 36 + p1i] = cc2[3] + bv1;
        }
    }
}

// ---------------------------------------------------------------------------
// squash over 1152 + transpose to hT (smem-staged, coalesced writes).
// ---------------------------------------------------------------------------
__global__ __launch_bounds__(256) void squash_h_kernel()
{
    int b = blockIdx.x;
    int tid = threadIdx.x;
    __shared__ float s_scale[8];
    __shared__ float s_val[9216];
    int g = tid >> 5;
    int lane = tid & 31;
    const float* pb = g_pc + (size_t)b * 9216;

    float ss = 0.f;
    for (int j = lane; j < 1152; j += 32) {
        float v = pb[g * 1152 + j];
        ss += v * v;
    }
    #pragma unroll
    for (int o = 16; o; o >>= 1) ss += __shfl_xor_sync(0xffffffffu, ss, o);
    if (lane == 0) s_scale[g] = sqrtf(ss) / (1.f + ss);
    __syncthreads();

    for (int idx = tid; idx < 9216; idx += 256)
        s_val[idx] = pb[idx] * s_scale[idx >> 10];   // idx/36 >> 5 == idx>>10? no
    __syncthreads();
    // fix: recompute scale index properly below (idx/36/32). Overwrite:
    __syncthreads();
    for (int idx = tid; idx < 9216; idx += 256) {
        int cch = idx / 36;
        s_val[idx] = pb[idx] * s_scale[cch >> 5];
    }
    __syncthreads();

    float* outb = g_hT + (size_t)b * 9216;
    for (int o = tid; o < 9216; o += 256) {
        int pos = o >> 3;
        int g2 = o & 7;
        int cch = g2 * 32 + pos / 36;
        int s = pos % 36;
        outb[o] = s_val[cch * 36 + s];
    }
}

// ---------------------------------------------------------------------------
// u_hat (fp16 out): grid 1152, block 256.
// ---------------------------------------------------------------------------
__global__ __launch_bounds__(256) void uhat_kernel(const float* __restrict__ W)
{
    int i = blockIdx.x;
    __shared__ float sW[1280];
    __shared__ float sh[32 * 8];
    int tid = threadIdx.x;
    for (int j = tid; j < 1280; j += 256)
        sW[(j & 7) * 160 + (j >> 3)] = W[(size_t)i * 1280 + j];

    for (int b0 = 0; b0 < BATCH; b0 += 32) {
        __syncthreads();
        sh[tid] = g_hT[((size_t)(b0 + (tid >> 3)) * 1152 + i) * 8 + (tid & 7)];
        __syncthreads();
        if (tid < 160) {
            #pragma unroll 4
            for (int bb = 0; bb < 32; bb++) {
                float u = 0.f;
                #pragma unroll
                for (int e = 0; e < 8; e++) u += sW[e * 160 + tid] * sh[bb * 8 + e];
                g_uhat[((size_t)(b0 + bb) * 1152 + i) * 160 + tid] = __float2half(u);
            }
        }
    }
}

// ---------------------------------------------------------------------------
__global__ __launch_bounds__(160) void routing0_kernel()
{
    int b = blockIdx.x;
    int t = threadIdx.x;
    for (int j = t; j < 11520; j += 160) g_blog[(size_t)b * 11520 + j] = 0.f;

    const __half* ub = g_uhat + (size_t)b * 184320;
    float s0 = 0.f, s1 = 0.f, s2 = 0.f, s3 = 0.f;
    for (int i = 0; i < 1152; i += 4) {
        s0 += __half2float(ub[(i + 0) * 160 + t]);
        s1 += __half2float(ub[(i + 1) * 160 + t]);
        s2 += __half2float(ub[(i + 2) * 160 + t]);
        s3 += __half2float(ub[(i + 3) * 160 + t]);
    }
    float s = 0.1f * (s0 + s1 + s2 + s3);

    __shared__ float s_s[160];
    s_s[t] = s;
    __syncthreads();
    int k = t >> 4;
    float n2 = 0.f;
    #pragma unroll
    for (int d = 0; d < 16; d++) {
        float v = s_s[k * 16 + d];
        n2 += v * v;
    }
    g_v[b * 160 + t] = s * (sqrtf(n2) / (1.f + n2));
}

// ---------------------------------------------------------------------------
__global__ __launch_bounds__(256) void routing_iter_kernel()
{
    int b = blockIdx.x;
    int t = threadIdx.x;
    __shared__ float v_s[160];
    __shared__ float c_s[1152 * 10];
    __shared__ float s_s[160];

    if (t < 160) v_s[t] = g_v[b * 160 + t];
    __syncthreads();

    const __half* ub = g_uhat + (size_t)b * 184320;
    float* blb = g_blog + (size_t)b * 11520;

    for (int i = t; i < 1152; i += 256) {
        const __half2* u2 = (const __half2*)(ub + i * 160);
        float bl[10];
        float mx = -1e30f;
        #pragma unroll
        for (int k = 0; k < 10; k++) {
            float dk = 0.f;
            #pragma unroll
            for (int j = 0; j < 8; j++) {
                float2 u = __half22float2(u2[k * 8 + j]);
                dk += u.x * v_s[k * 16 + 2 * j + 0];
                dk += u.y * v_s[k * 16 + 2 * j + 1];
            }
            float nb = blb[i * 10 + k] + dk;
            blb[i * 10 + k] = nb;
            bl[k] = nb;
            mx = fmaxf(mx, nb);
        }
        float sum = 0.f;
        #pragma unroll
        for (int k = 0; k < 10; k++) {
            float e = __expf(bl[k] - mx);
            bl[k] = e;
            sum += e;
        }
        float inv = 1.f / sum;
        #pragma unroll
        for (int k = 0; k < 10; k++) c_s[i * 10 + k] = bl[k] * inv;
    }
    __syncthreads();

    float s = 0.f;
    if (t < 160) {
        int k = t >> 4;
        float p0 = 0.f, p1 = 0.f;
        for (int i = 0; i < 1152; i += 2) {
            p0 += c_s[(i + 0) * 10 + k] * __half2float(__ldg(ub + (i + 0) * 160 + t));
            p1 += c_s[(i + 1) * 10 + k] * __half2float(__ldg(ub + (i + 1) * 160 + t));
        }
        s = p0 + p1;
    }
    __syncthreads();
    if (t < 160) s_s[t] = s;
    __syncthreads();
    if (t < 160) {
        int k = t >> 4;
        float n2 = 0.f;
        #pragma unroll
        for (int d = 0; d < 16; d++) {
            float v = s_s[k * 16 + d];
            n2 += v * v;
        }
        g_v[b * 160 + t] = s * (sqrtf(n2) / (1.f + n2));
    }
}

// ---------------------------------------------------------------------------
__global__ void mask_kernel(const float* __restrict__ labels)
{
    int idx = blockIdx.x * 256 + threadIdx.x;
    if (idx < BATCH * 160) {
        int b = idx / 160;
        int k = (idx - b * 160) >> 4;
        g_m[idx] = g_v[idx] * labels[b * 10 + k];
    }
}

// ---------------------------------------------------------------------------
template <int ACT, int SEL>
__global__ __launch_bounds__(256) void gemm_kernel(
    const float* __restrict__ Wt, const float* __restrict__ bias,
    float* __restrict__ outp, int M, int N, int K)
{
    const float* A = (SEL == 0) ? g_m : (SEL == 1) ? g_fc1 : g_fc2;
    float* C = (SEL == 0) ? g_fc1 : (SEL == 1) ? g_fc2 : outp;

    __shared__ float As[8][64];
    __shared__ float Bs[8][64];
    int n0 = blockIdx.x * 64;
    int m0 = blockIdx.y * 64;
    int tid = threadIdx.x;
    int tx = tid & 15;
    int ty = tid >> 4;

    float acc[4][4];
    #pragma unroll
    for (int i = 0; i < 4; i++)
        #pragma unroll
        for (int j = 0; j < 4; j++) acc[i][j] = 0.f;

    for (int k0 = 0; k0 < K; k0 += 8) {
        __syncthreads();
        #pragma unroll
        for (int l = 0; l < 2; l++) {
            int e = tid + l * 256;
            int r = e >> 3;
            int kk = e & 7;
            As[kk][r] = A[(m0 + r) * K + k0 + kk];
            int n = n0 + r;
            Bs[kk][r] = (n < N) ? Wt[n * K + k0 + kk] : 0.f;
        }
        __syncthreads();
        #pragma unroll
        for (int kk = 0; kk < 8; kk++) {
            float4 a4 = *(const float4*)&As[kk][ty * 4];
            float4 b4 = *(const float4*)&Bs[kk][tx * 4];
            float a[4] = {a4.x, a4.y, a4.z, a4.w};
            float bb[4] = {b4.x, b4.y, b4.z, b4.w};
            #pragma unroll
            for (int i = 0; i < 4; i++)
                #pragma unroll
                for (int j = 0; j < 4; j++) acc[i][j] += a[i] * bb[j];
        }
    }

    #pragma unroll
    for (int i = 0; i < 4; i++) {
        int m = m0 + ty * 4 + i;
        #pragma unroll
        for (int j = 0; j < 4; j++) {
            int n = n0 + tx * 4 + j;
            if (n < N) {
                float v = acc[i][j] + bias[n];
                if (ACT == 0) v = fmaxf(v, 0.f);
                else v = 1.f / (1.f + __expf(-v));
                C[m * N + n] = v;
            }
        }
    }
}

// ---------------------------------------------------------------------------
__global__ void probs_kernel(float* __restrict__ out)
{
    int b = blockIdx.x * 128 + threadIdx.x;
    if (b < BATCH) {
        float nr[10];
        float mx = -1e30f;
        #pragma unroll
        for (int k = 0; k < 10; k++) {
            float n2 = 0.f;
            #pragma unroll
            for (int d = 0; d < 16; d++) {
                float v = g_v[b * 160 + k * 16 + d];
                n2 += v * v;
            }
            nr[k] = sqrtf(n2);
            mx = fmaxf(mx, nr[k]);
        }
        float sum = 0.f;
        #pragma unroll
        for (int k = 0; k < 10; k++) {
            nr[k] = __expf(nr[k] - mx);
            sum += nr[k];
        }
        float inv = 1.f / sum;
        #pragma unroll
        for (int k = 0; k < 10; k++) out[b * 10 + k] = nr[k] * inv;
    }
}

// ---------------------------------------------------------------------------
extern "C" void kernel_launch(void* const* d_in, const int* in_sizes, int n_in,
                              void* d_out, int out_size)
{
    const float* x       = (const float*)d_in[0];
    const float* labels  = (const float*)d_in[1];
    const float* conv1_w = (const float*)d_in[2];
    const float* conv1_b = (const float*)d_in[3];
    const float* pc_w    = (const float*)d_in[4];
    const float* pc_b    = (const float*)d_in[5];
    const float* W       = (const float*)d_in[6];
    const float* fc1_w   = (const float*)d_in[7];
    const float* fc1_b   = (const float*)d_in[8];
    const float* fc2_w   = (const float*)d_in[9];
    const float* fc2_b   = (const float*)d_in[10];
    const float* fc3_w   = (const float*)d_in[11];
    const float* fc3_b   = (const float*)d_in[12];
    float* out = (float*)d_out;

    cudaFuncSetAttribute(pcgemm_kernel,
                         cudaFuncAttributeMaxDynamicSharedMemorySize, PCG_SMEM);
    cudaFuncSetAttribute(wrelayout_kernel,
                         cudaFuncAttributeMaxDynamicSharedMemorySize, 83968);

    conv1_kernel<<<dim3(BATCH, 4), 128>>>(x, conv1_w, conv1_b);
    wrelayout_kernel<<<256, 256, 83968>>>(pc_w);
    pcgemm_kernel<<<144, 256, PCG_SMEM>>>(pc_b);
    squash_h_kernel<<<BATCH, 256>>>();
    uhat_kernel<<<1152, 256>>>(W);
    routing0_kernel<<<BATCH, 160>>>();
    routing_iter_kernel<<<BATCH, 256>>>();
    routing_iter_kernel<<<BATCH, 256>>>();
    mask_kernel<<<320, 256>>>(labels);
    gemm_kernel<0, 0><<<dim3(8, 8), 256>>>(fc1_w, fc1_b, out, 512, 512, 160);
    gemm_kernel<0, 1><<<dim3(16, 8), 256>>>(fc2_w, fc2_b, out, 512, 1024, 512);
    gemm_kernel<1, 2><<<dim3(13, 8), 256>>>(fc3_w, fc3_b, out + 5120, 512, 784, 1024);
    probs_kernel<<<4, 128>>>(out);
}

// round 6
// speedup vs baseline: 5.1881x; 1.4639x over previous
#include <cuda_runtime.h>
#include <cuda_bf16.h>
#include <cuda_fp16.h>
#include <cstdint>
#include <math.h>

// ---------------------------------------------------------------------------
// CapsNet forward. B=512.
//   conv1:  [512,1,28,28] -> relu -> channel-last fp16 [b,iy,ix,ic]
//   pcconv: fp16 mma.sync implicit GEMM (cp.async 2-stage, M=128 N=256 /CTA)
//   squash over 1152 -> hT; u_hat (fp16 storage); routing x3; decoder; probs
// Output: [probs (512*10)] then [dec (512*784)]
// ---------------------------------------------------------------------------

#define BATCH 512

__device__ __half g_cl[BATCH * 400 * 256];        // conv1 out, channel-last fp16
__device__ __half g_wr[256 * 81 * 256];           // pc weights [oc][tap][ic] fp16
__device__ float g_pc[BATCH * 256 * 36];
__device__ float g_hT[BATCH * 1152 * 8];
__device__ __half g_uhat[BATCH * 1152 * 160];     // fp16 storage
__device__ float g_blog[BATCH * 1152 * 10];
__device__ float g_v[BATCH * 160];
__device__ float g_m[BATCH * 160];
__device__ float g_fc1[BATCH * 512];
__device__ float g_fc2[BATCH * 1024];

// ---------------- helpers ---------------------------------------------------
__device__ __forceinline__ uint32_t smem_u32(const void* p) {
    uint32_t a;
    asm("{ .reg .u64 t; cvta.to.shared.u64 t, %1; cvt.u32.u64 %0, t; }"
        : "=r"(a) : "l"(p));
    return a;
}
__device__ __forceinline__ void ldsm_x4(uint32_t& d0, uint32_t& d1,
                                        uint32_t& d2, uint32_t& d3,
                                        uint32_t addr) {
    asm volatile("ldmatrix.sync.aligned.m8n8.x4.shared.b16 {%0,%1,%2,%3}, [%4];"
                 : "=r"(d0), "=r"(d1), "=r"(d2), "=r"(d3) : "r"(addr));
}
__device__ __forceinline__ void mma16816h(float* c, const uint32_t* a,
                                          const uint32_t* b) {
    asm volatile(
        "mma.sync.aligned.m16n8k16.row.col.f32.f16.f16.f32 "
        "{%0,%1,%2,%3}, {%4,%5,%6,%7}, {%8,%9}, {%0,%1,%2,%3};"
        : "+f"(c[0]), "+f"(c[1]), "+f"(c[2]), "+f"(c[3])
        : "r"(a[0]), "r"(a[1]), "r"(a[2]), "r"(a[3]), "r"(b[0]), "r"(b[1]));
}
#define CP16(dst, src) \
    asm volatile("cp.async.cg.shared.global [%0], [%1], 16;" \
                 :: "r"(dst), "l"(src) : "memory")
#define CP_COMMIT() asm volatile("cp.async.commit_group;" ::: "memory")
#define CP_WAIT1() asm volatile("cp.async.wait_group 1;" ::: "memory")
#define CP_WAIT0() asm volatile("cp.async.wait_group 0;" ::: "memory")

// fp32x2 helpers for conv1
__device__ __forceinline__ void ffma2(unsigned long long& d,
                                      unsigned long long a,
                                      unsigned long long b) {
    asm("fma.rn.f32x2 %0, %1, %2, %0;" : "+l"(d) : "l"(a), "l"(b));
}
__device__ __forceinline__ unsigned long long pack2(float v) {
    unsigned long long r;
    asm("mov.b64 %0, {%1, %2};" : "=l"(r) : "f"(v), "f"(v));
    return r;
}
__device__ __forceinline__ void unpack2(unsigned long long p, float& lo, float& hi) {
    asm("mov.b64 {%0, %1}, %2;" : "=f"(lo), "=f"(hi) : "l"(p));
}

#define CW 68

// ---------------------------------------------------------------------------
// conv1: 1->256, 9x9, valid, relu -> channel-last fp16. grid (512,4), blk 128.
// ---------------------------------------------------------------------------
__global__ __launch_bounds__(128, 4) void conv1_kernel(
    const float* __restrict__ x, const float* __restrict__ w,
    const float* __restrict__ bias)
{
    int b = blockIdx.x;
    int ocg = blockIdx.y;
    __shared__ float s_img[784];
    __shared__ float s_w[81 * CW];
    int tid = threadIdx.x;

    for (int i = tid; i < 196; i += 128)
        *(float4*)&s_img[i * 4] = *(const float4*)&x[b * 784 + i * 4];
    for (int i = tid; i < 64 * 81; i += 128) {
        int r = i / 81;
        int e = i - r * 81;
        s_w[e * CW + r] = w[(ocg * 64 + r) * 81 + e];
    }
    __syncthreads();

    int ocp = tid & 31;
    int yg = tid >> 5;
    int oc0 = ocg * 64 + ocp * 2;
    float bv0 = bias[oc0], bv1 = bias[oc0 + 1];

    for (int yi = 0; yi < 5; yi++) {
        int y = yg * 5 + yi;
        unsigned long long acc[20];
        #pragma unroll
        for (int xx = 0; xx < 20; xx++) acc[xx] = 0ull;

        for (int ky = 0; ky < 9; ky++) {
            const float* rowp = s_img + (y + ky) * 28;
            unsigned long long rp[28];
            #pragma unroll
            for (int q = 0; q < 7; q++) {
                float4 r4 = *(const float4*)(rowp + q * 4);
                rp[q * 4 + 0] = pack2(r4.x);
                rp[q * 4 + 1] = pack2(r4.y);
                rp[q * 4 + 2] = pack2(r4.z);
                rp[q * 4 + 3] = pack2(r4.w);
            }
            #pragma unroll
            for (int kx = 0; kx < 9; kx++) {
                unsigned long long wp =
                    *(const unsigned long long*)(s_w + (ky * 9 + kx) * CW + ocp * 2);
                #pragma unroll
                for (int xx = 0; xx < 20; xx++) ffma2(acc[xx], wp, rp[xx + kx]);
            }
        }
        #pragma unroll
        for (int xx = 0; xx < 20; xx++) {
            float v0, v1;
            unpack2(acc[xx], v0, v1);
            v0 = fmaxf(v0 + bv0, 0.f);
            v1 = fmaxf(v1 + bv1, 0.f);
            int idx32 = ((b * 20 + y) * 20 + xx) * 128 + ocg * 32 + ocp;
            ((__half2*)g_cl)[idx32] = __floats2half2_rn(v0, v1);
        }
    }
}

// ---------------------------------------------------------------------------
// weight relayout via smem transpose: pc_w [oc][ic][81] -> g_wr [oc][tap][ic]
// grid 256, block 256, dynamic smem 42KB.
// ---------------------------------------------------------------------------
__global__ __launch_bounds__(256) void wrelayout_kernel(const float* __restrict__ w)
{
    extern __shared__ char wsm[];
    __half* sh = (__half*)wsm;
    int oc = blockIdx.x;
    int tid = threadIdx.x;
    const float* src = w + (size_t)oc * 20736;

    for (int j = tid; j < 20736; j += 256) {
        int ic = j / 81;
        int e = j - ic * 81;
        sh[e * 256 + ic] = __float2half(src[j]);
    }
    __syncthreads();

    uint4* dh = (uint4*)(g_wr + (size_t)oc * 20736);
    const uint4* s4 = (const uint4*)sh;
    for (int j = tid; j < 2592; j += 256) dh[j] = s4[j];
}

// ---------------------------------------------------------------------------
// pcconv: fp16 implicit GEMM, cp.async 2-stage, M=128 x N=256 per CTA.
// grid 144, block 256 (8 warps 4(M)x2(N)). K = 81 taps x 4 ic-chunks of 64.
// ---------------------------------------------------------------------------
#define SM_A 0
#define SM_B 16384
#define STAGE 49152
#define PCG_SMEM (2 * STAGE)

__global__ __launch_bounds__(256, 1) void pcgemm_kernel(const float* __restrict__ bias)
{
    extern __shared__ char sm[];
    __shared__ int s_rowbase[128];

    int tid = threadIdx.x;
    int wid = tid >> 5;
    int lane = tid & 31;
    int warp_m = wid & 3;
    int warp_n = wid >> 2;
    int m0 = blockIdx.x * 128;
    uint32_t smb = smem_u32(sm);

    if (tid < 128) {
        int npos = m0 + tid;
        int b = npos / 36;
        int pos = npos - b * 36;
        int y = pos / 6;
        int xq = pos - y * 6;
        s_rowbase[tid] = ((b * 20 + 2 * y) * 20 + 2 * xq) * 256;
    }
    __syncthreads();

    int r0 = tid >> 3;   // 0..31
    int c = tid & 7;
    uint32_t dbase = (uint32_t)(r0 * 128) + (uint32_t)((c * 16) ^ ((r0 & 7) << 4));
    int rb[4];
    #pragma unroll
    for (int i = 0; i < 4; i++) rb[i] = s_rowbase[r0 + 32 * i];
    int bbase0 = r0 * 20736;

#define PCG_ISSUE(K) do { \
    int _kykx = (K) >> 2; \
    int _ic0 = ((K) & 3) << 6; \
    int _ky = _kykx / 9; \
    int _kx = _kykx - _ky * 9; \
    int _asrc = (_ky * 20 + _kx) * 256 + _ic0 + c * 8; \
    int _bsrc = _kykx * 256 + _ic0 + c * 8; \
    uint32_t _st = smb + ((K) & 1) * STAGE; \
    _Pragma("unroll") \
    for (int _i = 0; _i < 4; _i++) \
        CP16(_st + SM_A + dbase + _i * 4096, g_cl + rb[_i] + _asrc); \
    _Pragma("unroll") \
    for (int _t = 0; _t < 8; _t++) \
        CP16(_st + SM_B + dbase + _t * 4096, g_wr + bbase0 + _t * 663552 + _bsrc); \
} while (0)

    float acc[2][16][4];
    #pragma unroll
    for (int i = 0; i < 2; i++)
        #pragma unroll
        for (int j = 0; j < 16; j++)
            #pragma unroll
            for (int k = 0; k < 4; k++) acc[i][j][k] = 0.f;

    uint32_t swz = (uint32_t)(lane & 7) << 4;
    uint32_t a_row_off = SM_A + (uint32_t)(warp_m * 32 + (lane & 15)) * 128;
    uint32_t akb = (uint32_t)(lane >> 4) << 4;
    uint32_t b_row_off = SM_B +
        (uint32_t)(warp_n * 128 + (lane & 7) + ((lane >> 4) & 1) * 8) * 128;
    uint32_t bkb = (uint32_t)((lane >> 3) & 1) << 4;

    PCG_ISSUE(0);
    CP_COMMIT();

    for (int kc = 0; kc < 324; kc++) {
        if (kc < 323) {
            PCG_ISSUE(kc + 1);
            CP_COMMIT();
            CP_WAIT1();
        } else {
            CP_WAIT0();
        }
        __syncthreads();

        uint32_t st = smb + (kc & 1) * STAGE;
        uint32_t a_row = st + a_row_off;
        uint32_t b_row = st + b_row_off;
        #pragma unroll
        for (int j = 0; j < 4; j++) {
            uint32_t ka = ((uint32_t)(j * 32) + akb) ^ swz;
            uint32_t ah[8];
            ldsm_x4(ah[0], ah[1], ah[2], ah[3], a_row + ka);
            ldsm_x4(ah[4], ah[5], ah[6], ah[7], a_row + 2048 + ka);
            uint32_t kb = ((uint32_t)(j * 32) + bkb) ^ swz;
            #pragma unroll
            for (int h = 0; h < 2; h++) {
                uint32_t bh[16];
                #pragma unroll
                for (int q = 0; q < 4; q++) {
                    uint32_t bt = b_row + (uint32_t)((h * 4 + q) * 2048) + kb;
                    ldsm_x4(bh[4 * q], bh[4 * q + 1], bh[4 * q + 2], bh[4 * q + 3], bt);
                }
                #pragma unroll
                for (int q = 0; q < 4; q++) {
                    #pragma unroll
                    for (int sub = 0; sub < 2; sub++) {
                        int nn = h * 8 + q * 2 + sub;
                        #pragma unroll
                        for (int tm = 0; tm < 2; tm++)
                            mma16816h(acc[tm][nn], &ah[4 * tm], &bh[4 * q + 2 * sub]);
                    }
                }
            }
        }
        __syncthreads();
    }

    // epilogue
    int r_in8 = lane >> 2;
    int c_in8 = (lane & 3) * 2;
    #pragma unroll
    for (int tm = 0; tm < 2; tm++) {
        int row0 = m0 + warp_m * 32 + tm * 16 + r_in8;
        int b0i = row0 / 36, p0i = row0 - b0i * 36;
        int row1 = row0 + 8;
        int b1i = row1 / 36, p1i = row1 - b1i * 36;
        #pragma unroll
        for (int nn = 0; nn < 16; nn++) {
            int col = warp_n * 128 + nn * 8 + c_in8;
            float bv0 = __ldg(bias + col);
            float bv1 = __ldg(bias + col + 1);
            const float* cc2 = acc[tm][nn];
            g_pc[b0i * 9216 + col * 36 + p0i] = cc2[0] + bv0;
            g_pc[b0i * 9216 + (col + 1) * 36 + p0i] = cc2[1] + bv1;
            g_pc[b1i * 9216 + col * 36 + p1i] = cc2[2] + bv0;
            g_pc[b1i * 9216 + (col + 1) * 36 + p1i] = cc2[3] + bv1;
        }
    }
}

// ---------------------------------------------------------------------------
// squash over 1152 + transpose to hT (smem-staged, coalesced writes).
// ---------------------------------------------------------------------------
__global__ __launch_bounds__(256) void squash_h_kernel()
{
    int b = blockIdx.x;
    int tid = threadIdx.x;
    __shared__ float s_scale[8];
    __shared__ float s_val[9216];
    int g = tid >> 5;
    int lane = tid & 31;
    const float* pb = g_pc + (size_t)b * 9216;

    float ss = 0.f;
    for (int j = lane; j < 1152; j += 32) {
        float v = pb[g * 1152 + j];
        ss += v * v;
    }
    #pragma unroll
    for (int o = 16; o; o >>= 1) ss += __shfl_xor_sync(0xffffffffu, ss, o);
    if (lane == 0) s_scale[g] = sqrtf(ss) / (1.f + ss);
    __syncthreads();

    for (int idx = tid; idx < 9216; idx += 256) {
        int cch = idx / 36;
        s_val[idx] = pb[idx] * s_scale[cch >> 5];
    }
    __syncthreads();

    float* outb = g_hT + (size_t)b * 9216;
    for (int o = tid; o < 9216; o += 256) {
        int pos = o >> 3;
        int g2 = o & 7;
        int cch = g2 * 32 + pos / 36;
        int s = pos % 36;
        outb[o] = s_val[cch * 36 + s];
    }
}

// ---------------------------------------------------------------------------
// u_hat (fp16 out): grid 1152, block 256.
// ---------------------------------------------------------------------------
__global__ __launch_bounds__(256) void uhat_kernel(const float* __restrict__ W)
{
    int i = blockIdx.x;
    __shared__ float sW[1280];
    __shared__ float sh[32 * 8];
    int tid = threadIdx.x;
    for (int j = tid; j < 1280; j += 256)
        sW[(j & 7) * 160 + (j >> 3)] = W[(size_t)i * 1280 + j];

    for (int b0 = 0; b0 < BATCH; b0 += 32) {
        __syncthreads();
        sh[tid] = g_hT[((size_t)(b0 + (tid >> 3)) * 1152 + i) * 8 + (tid & 7)];
        __syncthreads();
        if (tid < 160) {
            #pragma unroll 4
            for (int bb = 0; bb < 32; bb++) {
                float u = 0.f;
                #pragma unroll
                for (int e = 0; e < 8; e++) u += sW[e * 160 + tid] * sh[bb * 8 + e];
                g_uhat[((size_t)(b0 + bb) * 1152 + i) * 160 + tid] = __float2half(u);
            }
        }
    }
}

// ---------------------------------------------------------------------------
__global__ __launch_bounds__(160) void routing0_kernel()
{
    int b = blockIdx.x;
    int t = threadIdx.x;
    for (int j = t; j < 11520; j += 160) g_blog[(size_t)b * 11520 + j] = 0.f;

    const __half* ub = g_uhat + (size_t)b * 184320;
    float s0 = 0.f, s1 = 0.f, s2 = 0.f, s3 = 0.f;
    for (int i = 0; i < 1152; i += 4) {
        s0 += __half2float(ub[(i + 0) * 160 + t]);
        s1 += __half2float(ub[(i + 1) * 160 + t]);
        s2 += __half2float(ub[(i + 2) * 160 + t]);
        s3 += __half2float(ub[(i + 3) * 160 + t]);
    }
    float s = 0.1f * (s0 + s1 + s2 + s3);

    __shared__ float s_s[160];
    s_s[t] = s;
    __syncthreads();
    int k = t >> 4;
    float n2 = 0.f;
    #pragma unroll
    for (int d = 0; d < 16; d++) {
        float v = s_s[k * 16 + d];
        n2 += v * v;
    }
    g_v[b * 160 + t] = s * (sqrtf(n2) / (1.f + n2));
}

// ---------------------------------------------------------------------------
__global__ __launch_bounds__(256) void routing_iter_kernel()
{
    int b = blockIdx.x;
    int t = threadIdx.x;
    __shared__ float v_s[160];
    __shared__ float c_s[1152 * 10];
    __shared__ float s_s[160];

    if (t < 160) v_s[t] = g_v[b * 160 + t];
    __syncthreads();

    const __half* ub = g_uhat + (size_t)b * 184320;
    float* blb = g_blog + (size_t)b * 11520;

    for (int i = t; i < 1152; i += 256) {
        const __half2* u2 = (const __half2*)(ub + i * 160);
        float bl[10];
        float mx = -1e30f;
        #pragma unroll
        for (int k = 0; k < 10; k++) {
            float dk = 0.f;
            #pragma unroll
            for (int j = 0; j < 8; j++) {
                float2 u = __half22float2(u2[k * 8 + j]);
                dk += u.x * v_s[k * 16 + 2 * j + 0];
                dk += u.y * v_s[k * 16 + 2 * j + 1];
            }
            float nb = blb[i * 10 + k] + dk;
            blb[i * 10 + k] = nb;
            bl[k] = nb;
            mx = fmaxf(mx, nb);
        }
        float sum = 0.f;
        #pragma unroll
        for (int k = 0; k < 10; k++) {
            float e = __expf(bl[k] - mx);
            bl[k] = e;
            sum += e;
        }
        float inv = 1.f / sum;
        #pragma unroll
        for (int k = 0; k < 10; k++) c_s[i * 10 + k] = bl[k] * inv;
    }
    __syncthreads();

    float s = 0.f;
    if (t < 160) {
        int k = t >> 4;
        float p0 = 0.f, p1 = 0.f;
        #pragma unroll 4
        for (int i = 0; i < 1152; i += 2) {
            p0 += c_s[(i + 0) * 10 + k] * __half2float(__ldg(ub + (i + 0) * 160 + t));
            p1 += c_s[(i + 1) * 10 + k] * __half2float(__ldg(ub + (i + 1) * 160 + t));
        }
        s = p0 + p1;
    }
    __syncthreads();
    if (t < 160) s_s[t] = s;
    __syncthreads();
    if (t < 160) {
        int k = t >> 4;
        float n2 = 0.f;
        #pragma unroll
        for (int d = 0; d < 16; d++) {
            float v = s_s[k * 16 + d];
            n2 += v * v;
        }
        g_v[b * 160 + t] = s * (sqrtf(n2) / (1.f + n2));
    }
}

// ---------------------------------------------------------------------------
__global__ void mask_kernel(const float* __restrict__ labels)
{
    int idx = blockIdx.x * 256 + threadIdx.x;
    if (idx < BATCH * 160) {
        int b = idx / 160;
        int k = (idx - b * 160) >> 4;
        g_m[idx] = g_v[idx] * labels[b * 10 + k];
    }
}

// ---------------------------------------------------------------------------
template <int ACT, int SEL>
__global__ __launch_bounds__(256) void gemm_kernel(
    const float* __restrict__ Wt, const float* __restrict__ bias,
    float* __restrict__ outp, int M, int N, int K)
{
    const float* A = (SEL == 0) ? g_m : (SEL == 1) ? g_fc1 : g_fc2;
    float* C = (SEL == 0) ? g_fc1 : (SEL == 1) ? g_fc2 : outp;

    __shared__ float As[8][64];
    __shared__ float Bs[8][64];
    int n0 = blockIdx.x * 64;
    int m0 = blockIdx.y * 64;
    int tid = threadIdx.x;
    int tx = tid & 15;
    int ty = tid >> 4;

    float acc[4][4];
    #pragma unroll
    for (int i = 0; i < 4; i++)
        #pragma unroll
        for (int j = 0; j < 4; j++) acc[i][j] = 0.f;

    for (int k0 = 0; k0 < K; k0 += 8) {
        __syncthreads();
        #pragma unroll
        for (int l = 0; l < 2; l++) {
            int e = tid + l * 256;
            int r = e >> 3;
            int kk = e & 7;
            As[kk][r] = A[(m0 + r) * K + k0 + kk];
            int n = n0 + r;
            Bs[kk][r] = (n < N) ? Wt[n * K + k0 + kk] : 0.f;
        }
        __syncthreads();
        #pragma unroll
        for (int kk = 0; kk < 8; kk++) {
            float4 a4 = *(const float4*)&As[kk][ty * 4];
            float4 b4 = *(const float4*)&Bs[kk][tx * 4];
            float a[4] = {a4.x, a4.y, a4.z, a4.w};
            float bb[4] = {b4.x, b4.y, b4.z, b4.w};
            #pragma unroll
            for (int i = 0; i < 4; i++)
                #pragma unroll
                for (int j = 0; j < 4; j++) acc[i][j] += a[i] * bb[j];
        }
    }

    #pragma unroll
    for (int i = 0; i < 4; i++) {
        int m = m0 + ty * 4 + i;
        #pragma unroll
        for (int j = 0; j < 4; j++) {
            int n = n0 + tx * 4 + j;
            if (n < N) {
                float v = acc[i][j] + bias[n];
                if (ACT == 0) v = fmaxf(v, 0.f);
                else v = 1.f / (1.f + __expf(-v));
                C[m * N + n] = v;
            }
        }
    }
}

// ---------------------------------------------------------------------------
__global__ void probs_kernel(float* __restrict__ out)
{
    int b = blockIdx.x * 128 + threadIdx.x;
    if (b < BATCH) {
        float nr[10];
        float mx = -1e30f;
        #pragma unroll
        for (int k = 0; k < 10; k++) {
            float n2 = 0.f;
            #pragma unroll
            for (int d = 0; d < 16; d++) {
                float v = g_v[b * 160 + k * 16 + d];
                n2 += v * v;
            }
            nr[k] = sqrtf(n2);
            mx = fmaxf(mx, nr[k]);
        }
        float sum = 0.f;
        #pragma unroll
        for (int k = 0; k < 10; k++) {
            nr[k] = __expf(nr[k] - mx);
            sum += nr[k];
        }
        float inv = 1.f / sum;
        #pragma unroll
        for (int k = 0; k < 10; k++) out[b * 10 + k] = nr[k] * inv;
    }
}

// ---------------------------------------------------------------------------
extern "C" void kernel_launch(void* const* d_in, const int* in_sizes, int n_in,
                              void* d_out, int out_size)
{
    const float* x       = (const float*)d_in[0];
    const float* labels  = (const float*)d_in[1];
    const float* conv1_w = (const float*)d_in[2];
    const float* conv1_b = (const float*)d_in[3];
    const float* pc_w    = (const float*)d_in[4];
    const float* pc_b    = (const float*)d_in[5];
    const float* W       = (const float*)d_in[6];
    const float* fc1_w   = (const float*)d_in[7];
    const float* fc1_b   = (const float*)d_in[8];
    const float* fc2_w   = (const float*)d_in[9];
    const float* fc2_b   = (const float*)d_in[10];
    const float* fc3_w   = (const float*)d_in[11];
    const float* fc3_b   = (const float*)d_in[12];
    float* out = (float*)d_out;

    cudaFuncSetAttribute(pcgemm_kernel,
                         cudaFuncAttributeMaxDynamicSharedMemorySize, PCG_SMEM);
    cudaFuncSetAttribute(wrelayout_kernel,
                         cudaFuncAttributeMaxDynamicSharedMemorySize, 43008);

    conv1_kernel<<<dim3(BATCH, 4), 128>>>(x, conv1_w, conv1_b);
    wrelayout_kernel<<<256, 256, 43008>>>(pc_w);
    pcgemm_kernel<<<144, 256, PCG_SMEM>>>(pc_b);
    squash_h_kernel<<<BATCH, 256>>>();
    uhat_kernel<<<1152, 256>>>(W);
    routing0_kernel<<<BATCH, 160>>>();
    routing_iter_kernel<<<BATCH, 256>>>();
    routing_iter_kernel<<<BATCH, 256>>>();
    mask_kernel<<<320, 256>>>(labels);
    gemm_kernel<0, 0><<<dim3(8, 8), 256>>>(fc1_w, fc1_b, out, 512, 512, 160);
    gemm_kernel<0, 1><<<dim3(16, 8), 256>>>(fc2_w, fc2_b, out, 512, 1024, 512);
    gemm_kernel<1, 2><<<dim3(13, 8), 256>>>(fc3_w, fc3_b, out + 5120, 512, 784, 1024);
    probs_kernel<<<4, 128>>>(out);
}